// round 1
// baseline (speedup 1.0000x reference)
#include <cuda_runtime.h>
#include <math.h>

// ---------------------------------------------------------------------------
// TensorParallelAttention baseline (fp32 FFMA), 5 launches:
//   1-3. Q/K/V = hidden @ W^T            (gemm_nt, M=4096 N=2048 K=2048)
//   4.   S     = scale * Q @ K^T         (gemm_nt batched z=32, K=128)
//   5.   softmax rows (+mask)
//   6.   A     = S @ V                   (gemm_nn batched z=32, N=128)
//   7.   out   = A @ Wo^T                (gemm_nt)
// Scratch in __device__ globals (no allocations, graph-capturable).
// ---------------------------------------------------------------------------

#define BM 128
#define BN 128
#define BK 16

#define HID 2048
#define MROWS 4096                      // B*S
#define SB 4194304L                     // 2048*2048 per-(b,h) score matrix

__device__ float g_q[MROWS * HID];
__device__ float g_k[MROWS * HID];
__device__ float g_v[MROWS * HID];
__device__ float g_att[MROWS * HID];
__device__ float g_scores[32L * SB];    // 512 MB

// C[M,N] = alpha * A @ op(B)
//   TRANS_B=true : B stored [N,K] K-contiguous (i.e. C = A @ B^T, torch Linear)
//   TRANS_B=false: B stored [K,N] N-contiguous (i.e. C = A @ B)
// Batched via blockIdx.z with z = zb*16 + zh; per-operand offset zb*s1 + zh*s2.
template <bool TRANS_B>
__global__ __launch_bounds__(256, 2)
void gemm_f32(const float* __restrict__ A, const float* __restrict__ B,
              float* __restrict__ C,
              int K, int lda, int ldb, int ldc,
              long sA1, long sA2, long sB1, long sB2, long sC1, long sC2,
              float alpha)
{
    __shared__ float As[BK][BM + 4];
    __shared__ float Bs[BK][BN + 4];

    const int tid = threadIdx.x;
    const long zb = (long)(blockIdx.z >> 4);
    const long zh = (long)(blockIdx.z & 15);
    A += zb * sA1 + zh * sA2;
    B += zb * sB1 + zh * sB2;
    C += zb * sC1 + zh * sC2;

    const int bm = blockIdx.y * BM;
    const int bn = blockIdx.x * BN;

    const int tx = tid & 15;   // 16 cols of threads
    const int ty = tid >> 4;   // 16 rows of threads

    float acc[8][8];
#pragma unroll
    for (int i = 0; i < 8; i++)
#pragma unroll
        for (int j = 0; j < 8; j++) acc[i][j] = 0.0f;

    for (int k0 = 0; k0 < K; k0 += BK) {
        // ---- load A tile [BM x BK], store transposed As[k][m] ----
#pragma unroll
        for (int i = 0; i < 2; i++) {
            int idx = tid + i * 256;
            int r   = idx >> 2;          // 0..127
            int c   = (idx & 3) * 4;     // 0,4,8,12
            float4 va = *(const float4*)&A[(long)(bm + r) * lda + (k0 + c)];
            As[c + 0][r] = va.x; As[c + 1][r] = va.y;
            As[c + 2][r] = va.z; As[c + 3][r] = va.w;
            if (TRANS_B) {
                float4 vb = *(const float4*)&B[(long)(bn + r) * ldb + (k0 + c)];
                Bs[c + 0][r] = vb.x; Bs[c + 1][r] = vb.y;
                Bs[c + 2][r] = vb.z; Bs[c + 3][r] = vb.w;
            } else {
                int rb = idx >> 5;           // 0..15
                int cb = (idx & 31) * 4;     // 0..124
                float4 vb = *(const float4*)&B[(long)(k0 + rb) * ldb + (bn + cb)];
                *(float4*)&Bs[rb][cb] = vb;
            }
        }
        __syncthreads();

        // ---- compute: each thread 8x8, split rows/cols {t*4..t*4+3} u {64+t*4..} ----
#pragma unroll
        for (int k = 0; k < BK; k++) {
            float a[8], b[8];
            *(float4*)&a[0] = *(const float4*)&As[k][ty * 4];
            *(float4*)&a[4] = *(const float4*)&As[k][64 + ty * 4];
            *(float4*)&b[0] = *(const float4*)&Bs[k][tx * 4];
            *(float4*)&b[4] = *(const float4*)&Bs[k][64 + tx * 4];
#pragma unroll
            for (int i = 0; i < 8; i++)
#pragma unroll
                for (int j = 0; j < 8; j++)
                    acc[i][j] += a[i] * b[j];
        }
        __syncthreads();
    }

#pragma unroll
    for (int i = 0; i < 8; i++) {
        int r = bm + ((i < 4) ? (ty * 4 + i) : (64 + ty * 4 + (i - 4)));
        float4 v0 = make_float4(acc[i][0] * alpha, acc[i][1] * alpha,
                                acc[i][2] * alpha, acc[i][3] * alpha);
        float4 v1 = make_float4(acc[i][4] * alpha, acc[i][5] * alpha,
                                acc[i][6] * alpha, acc[i][7] * alpha);
        *(float4*)&C[(long)r * ldc + bn + tx * 4]      = v0;
        *(float4*)&C[(long)r * ldc + bn + 64 + tx * 4] = v1;
    }
}

// In-place softmax over rows of g_scores; row = z*2048 + q, adds mask[q, :].
__global__ __launch_bounds__(256)
void softmax_kernel(float* __restrict__ S, const float* __restrict__ mask)
{
    __shared__ float red[8];
    const long row = blockIdx.x;
    const int  q   = (int)(row & 2047);
    float* p = S + row * 2048L;
    const float* mr = mask + (long)q * 2048L;

    const int tid  = threadIdx.x;
    const int lane = tid & 31;
    const int wid  = tid >> 5;

    float v[8];
    float4 a0 = ((const float4*)p)[tid];
    float4 a1 = ((const float4*)p)[tid + 256];
    float4 m0 = ((const float4*)mr)[tid];
    float4 m1 = ((const float4*)mr)[tid + 256];
    v[0] = a0.x + m0.x; v[1] = a0.y + m0.y; v[2] = a0.z + m0.z; v[3] = a0.w + m0.w;
    v[4] = a1.x + m1.x; v[5] = a1.y + m1.y; v[6] = a1.z + m1.z; v[7] = a1.w + m1.w;

    float mx = v[0];
#pragma unroll
    for (int i = 1; i < 8; i++) mx = fmaxf(mx, v[i]);
#pragma unroll
    for (int o = 16; o > 0; o >>= 1)
        mx = fmaxf(mx, __shfl_xor_sync(0xffffffffu, mx, o));
    if (lane == 0) red[wid] = mx;
    __syncthreads();
    mx = red[0];
#pragma unroll
    for (int i = 1; i < 8; i++) mx = fmaxf(mx, red[i]);
    __syncthreads();

    float s = 0.0f;
#pragma unroll
    for (int i = 0; i < 8; i++) { v[i] = __expf(v[i] - mx); s += v[i]; }
#pragma unroll
    for (int o = 16; o > 0; o >>= 1)
        s += __shfl_xor_sync(0xffffffffu, s, o);
    if (lane == 0) red[wid] = s;
    __syncthreads();
    s = red[0];
#pragma unroll
    for (int i = 1; i < 8; i++) s += red[i];

    float inv = 1.0f / s;
    ((float4*)p)[tid]       = make_float4(v[0] * inv, v[1] * inv, v[2] * inv, v[3] * inv);
    ((float4*)p)[tid + 256] = make_float4(v[4] * inv, v[5] * inv, v[6] * inv, v[7] * inv);
}

extern "C" void kernel_launch(void* const* d_in, const int* in_sizes, int n_in,
                              void* d_out, int out_size)
{
    (void)in_sizes; (void)n_in; (void)out_size;
    const float* hidden = (const float*)d_in[0];
    const float* mask   = (const float*)d_in[1];
    const float* Wq     = (const float*)d_in[2];
    const float* Wk     = (const float*)d_in[3];
    const float* Wv     = (const float*)d_in[4];
    const float* Wo     = (const float*)d_in[5];
    float* out = (float*)d_out;

    float *q, *k, *v, *att, *sc;
    cudaGetSymbolAddress((void**)&q,   g_q);
    cudaGetSymbolAddress((void**)&k,   g_k);
    cudaGetSymbolAddress((void**)&v,   g_v);
    cudaGetSymbolAddress((void**)&att, g_att);
    cudaGetSymbolAddress((void**)&sc,  g_scores);

    dim3 thr(256);

    // 1-3: Q/K/V projections: [4096,2048] = hidden @ W^T
    dim3 gProj(HID / BN, MROWS / BM, 1);
    gemm_f32<true><<<gProj, thr>>>(hidden, Wq, q, HID, HID, HID, HID,
                                   0, 0, 0, 0, 0, 0, 1.0f);
    gemm_f32<true><<<gProj, thr>>>(hidden, Wk, k, HID, HID, HID, HID,
                                   0, 0, 0, 0, 0, 0, 1.0f);
    gemm_f32<true><<<gProj, thr>>>(hidden, Wv, v, HID, HID, HID, HID,
                                   0, 0, 0, 0, 0, 0, 1.0f);

    // 4: scores[z] = scale * Q_z @ K_z^T   (z = b*16 + h, 32 batches, K=128)
    dim3 gScore(2048 / BN, 2048 / BM, 32);
    gemm_f32<true><<<gScore, thr>>>(q, k, sc, 128, HID, HID, 2048,
                                    SB, 128, SB, 128, 16 * SB, SB,
                                    0.08838834764831845f);

    // 5: softmax over 32*2048 rows of length 2048 (adds mask)
    softmax_kernel<<<32 * 2048, 256>>>(sc, mask);

    // 6: att[z] = P_z @ V_z   (M=2048, N=128, K=2048), B is [K,N] layout
    dim3 gPV(128 / BN, 2048 / BM, 32);
    gemm_f32<false><<<gPV, thr>>>(sc, v, att, 2048, 2048, HID, HID,
                                  16 * SB, SB, SB, 128, SB, 128, 1.0f);

    // 7: out = att @ Wo^T
    gemm_f32<true><<<gProj, thr>>>(att, Wo, out, HID, HID, HID, HID,
                                   0, 0, 0, 0, 0, 0, 1.0f);
}

// round 2
// speedup vs baseline: 1.7953x; 1.7953x over previous
#include <cuda_runtime.h>
#include <math.h>

// ---------------------------------------------------------------------------
// TensorParallelAttention — tf32 mma.sync (tensor pipe) for all 5 GEMMs.
//   1-3. Q/K/V = hidden @ W^T            (M=4096 N=2048 K=2048)
//   4.   S     = scale * Q @ K^T         (batched z=32, K=128)
//   5.   softmax rows (+mask)
//   6.   A     = S @ V                   (batched z=32, N=128)
//   7.   out   = A @ Wo^T
// ---------------------------------------------------------------------------

#define BM 128
#define BN 128
#define BK 32
#define APAD 4
#define ASTRIDE (BM + APAD)   // 132 (uint32 units)

#define HID 2048
#define MROWS 4096
#define SB 4194304L

__device__ float g_q[MROWS * HID];
__device__ float g_k[MROWS * HID];
__device__ float g_v[MROWS * HID];
__device__ float g_att[MROWS * HID];
__device__ float g_scores[32L * SB];

__device__ __forceinline__ unsigned f2tf32(float f) {
    unsigned u;
    asm("cvt.rna.tf32.f32 %0, %1;" : "=r"(u) : "f"(f));
    return u;
}

// C[M,N] = alpha * A @ op(B); TRANS_B: B is [N,K] (k-contig), else [K,N].
template <bool TRANS_B>
__global__ __launch_bounds__(256, 2)
void gemm_tf32(const float* __restrict__ A, const float* __restrict__ B,
               float* __restrict__ C,
               int K, int lda, int ldb, int ldc,
               long sA1, long sA2, long sB1, long sB2, long sC1, long sC2,
               float alpha)
{
    __shared__ unsigned As[BK][ASTRIDE];
    __shared__ unsigned Bs[BK][ASTRIDE];

    const int tid  = threadIdx.x;
    const int lane = tid & 31;
    const int wid  = tid >> 5;
    const int grp  = lane >> 2;     // 0..7
    const int tig  = lane & 3;      // 0..3

    const int wm = wid & 1;         // 2 warps along M -> 64 rows each
    const int wn = wid >> 1;        // 4 warps along N -> 32 cols each

    const long zb = (long)(blockIdx.z >> 4);
    const long zh = (long)(blockIdx.z & 15);
    A += zb * sA1 + zh * sA2;
    B += zb * sB1 + zh * sB2;
    C += zb * sC1 + zh * sC2;

    const int bm = blockIdx.y * BM;
    const int bn = blockIdx.x * BN;

    float acc[4][4][4];
#pragma unroll
    for (int i = 0; i < 4; i++)
#pragma unroll
        for (int j = 0; j < 4; j++)
#pragma unroll
            for (int t = 0; t < 4; t++) acc[i][j][t] = 0.0f;

    for (int k0 = 0; k0 < K; k0 += BK) {
        // ---- A tile [BM x BK] -> As[k][m] (tf32), coalesced 128B loads ----
#pragma unroll
        for (int i = 0; i < 4; i++) {
            int linear = tid + i * 256;
            int r  = linear >> 3;          // 0..127
            int c4 = (linear & 7) * 4;     // 0..28
            float4 v = *(const float4*)&A[(long)(bm + r) * lda + (k0 + c4)];
            As[c4 + 0][r] = f2tf32(v.x);
            As[c4 + 1][r] = f2tf32(v.y);
            As[c4 + 2][r] = f2tf32(v.z);
            As[c4 + 3][r] = f2tf32(v.w);
        }
        // ---- B tile -> Bs[k][n] (tf32) ----
        if (TRANS_B) {
#pragma unroll
            for (int i = 0; i < 4; i++) {
                int linear = tid + i * 256;
                int r  = linear >> 3;
                int c4 = (linear & 7) * 4;
                float4 v = *(const float4*)&B[(long)(bn + r) * ldb + (k0 + c4)];
                Bs[c4 + 0][r] = f2tf32(v.x);
                Bs[c4 + 1][r] = f2tf32(v.y);
                Bs[c4 + 2][r] = f2tf32(v.z);
                Bs[c4 + 3][r] = f2tf32(v.w);
            }
        } else {
#pragma unroll
            for (int i = 0; i < 4; i++) {
                int linear = tid + i * 256;
                int rb = linear >> 5;           // 0..31
                int cb = (linear & 31) * 4;     // 0..124
                float4 v = *(const float4*)&B[(long)(k0 + rb) * ldb + (bn + cb)];
                Bs[rb][cb + 0] = f2tf32(v.x);
                Bs[rb][cb + 1] = f2tf32(v.y);
                Bs[rb][cb + 2] = f2tf32(v.z);
                Bs[rb][cb + 3] = f2tf32(v.w);
            }
        }
        __syncthreads();

#pragma unroll
        for (int kk = 0; kk < BK; kk += 8) {
            unsigned af[4][4], bf[4][2];
            const int mb = wm * 64;
            const int nb = wn * 32;
#pragma unroll
            for (int mt = 0; mt < 4; mt++) {
                int m = mb + mt * 16 + grp;
                af[mt][0] = As[kk + tig][m];
                af[mt][1] = As[kk + tig][m + 8];
                af[mt][2] = As[kk + tig + 4][m];
                af[mt][3] = As[kk + tig + 4][m + 8];
            }
#pragma unroll
            for (int nt = 0; nt < 4; nt++) {
                int n = nb + nt * 8 + grp;
                bf[nt][0] = Bs[kk + tig][n];
                bf[nt][1] = Bs[kk + tig + 4][n];
            }
#pragma unroll
            for (int mt = 0; mt < 4; mt++)
#pragma unroll
                for (int nt = 0; nt < 4; nt++) {
                    asm volatile(
                        "mma.sync.aligned.m16n8k8.row.col.f32.tf32.tf32.f32 "
                        "{%0,%1,%2,%3}, {%4,%5,%6,%7}, {%8,%9}, {%0,%1,%2,%3};"
                        : "+f"(acc[mt][nt][0]), "+f"(acc[mt][nt][1]),
                          "+f"(acc[mt][nt][2]), "+f"(acc[mt][nt][3])
                        : "r"(af[mt][0]), "r"(af[mt][1]),
                          "r"(af[mt][2]), "r"(af[mt][3]),
                          "r"(bf[nt][0]), "r"(bf[nt][1]));
                }
        }
        __syncthreads();
    }

    // ---- epilogue ----
#pragma unroll
    for (int mt = 0; mt < 4; mt++) {
        int r0 = bm + wm * 64 + mt * 16 + grp;
        int r1 = r0 + 8;
#pragma unroll
        for (int nt = 0; nt < 4; nt++) {
            int c = bn + wn * 32 + nt * 8 + tig * 2;
            float2 v0 = make_float2(acc[mt][nt][0] * alpha, acc[mt][nt][1] * alpha);
            float2 v1 = make_float2(acc[mt][nt][2] * alpha, acc[mt][nt][3] * alpha);
            *(float2*)&C[(long)r0 * ldc + c] = v0;
            *(float2*)&C[(long)r1 * ldc + c] = v1;
        }
    }
}

// In-place softmax over rows of g_scores; row = z*2048 + q, adds mask[q, :].
__global__ __launch_bounds__(256)
void softmax_kernel(float* __restrict__ S, const float* __restrict__ mask)
{
    __shared__ float red[8];
    const long row = blockIdx.x;
    const int  q   = (int)(row & 2047);
    float* p = S + row * 2048L;
    const float* mr = mask + (long)q * 2048L;

    const int tid  = threadIdx.x;
    const int lane = tid & 31;
    const int wid  = tid >> 5;

    float v[8];
    float4 a0 = ((const float4*)p)[tid];
    float4 a1 = ((const float4*)p)[tid + 256];
    float4 m0 = ((const float4*)mr)[tid];
    float4 m1 = ((const float4*)mr)[tid + 256];
    v[0] = a0.x + m0.x; v[1] = a0.y + m0.y; v[2] = a0.z + m0.z; v[3] = a0.w + m0.w;
    v[4] = a1.x + m1.x; v[5] = a1.y + m1.y; v[6] = a1.z + m1.z; v[7] = a1.w + m1.w;

    float mx = v[0];
#pragma unroll
    for (int i = 1; i < 8; i++) mx = fmaxf(mx, v[i]);
#pragma unroll
    for (int o = 16; o > 0; o >>= 1)
        mx = fmaxf(mx, __shfl_xor_sync(0xffffffffu, mx, o));
    if (lane == 0) red[wid] = mx;
    __syncthreads();
    mx = red[0];
#pragma unroll
    for (int i = 1; i < 8; i++) mx = fmaxf(mx, red[i]);
    __syncthreads();

    float s = 0.0f;
#pragma unroll
    for (int i = 0; i < 8; i++) { v[i] = __expf(v[i] - mx); s += v[i]; }
#pragma unroll
    for (int o = 16; o > 0; o >>= 1)
        s += __shfl_xor_sync(0xffffffffu, s, o);
    if (lane == 0) red[wid] = s;
    __syncthreads();
    s = red[0];
#pragma unroll
    for (int i = 1; i < 8; i++) s += red[i];

    float inv = 1.0f / s;
    ((float4*)p)[tid]       = make_float4(v[0] * inv, v[1] * inv, v[2] * inv, v[3] * inv);
    ((float4*)p)[tid + 256] = make_float4(v[4] * inv, v[5] * inv, v[6] * inv, v[7] * inv);
}

extern "C" void kernel_launch(void* const* d_in, const int* in_sizes, int n_in,
                              void* d_out, int out_size)
{
    (void)in_sizes; (void)n_in; (void)out_size;
    const float* hidden = (const float*)d_in[0];
    const float* mask   = (const float*)d_in[1];
    const float* Wq     = (const float*)d_in[2];
    const float* Wk     = (const float*)d_in[3];
    const float* Wv     = (const float*)d_in[4];
    const float* Wo     = (const float*)d_in[5];
    float* out = (float*)d_out;

    float *q, *k, *v, *att, *sc;
    cudaGetSymbolAddress((void**)&q,   g_q);
    cudaGetSymbolAddress((void**)&k,   g_k);
    cudaGetSymbolAddress((void**)&v,   g_v);
    cudaGetSymbolAddress((void**)&att, g_att);
    cudaGetSymbolAddress((void**)&sc,  g_scores);

    dim3 thr(256);

    // 1-3: Q/K/V projections
    dim3 gProj(HID / BN, MROWS / BM, 1);
    gemm_tf32<true><<<gProj, thr>>>(hidden, Wq, q, HID, HID, HID, HID,
                                    0, 0, 0, 0, 0, 0, 1.0f);
    gemm_tf32<true><<<gProj, thr>>>(hidden, Wk, k, HID, HID, HID, HID,
                                    0, 0, 0, 0, 0, 0, 1.0f);
    gemm_tf32<true><<<gProj, thr>>>(hidden, Wv, v, HID, HID, HID, HID,
                                    0, 0, 0, 0, 0, 0, 1.0f);

    // 4: scores = scale * Q @ K^T  (z = b*16 + h)
    dim3 gScore(2048 / BN, 2048 / BM, 32);
    gemm_tf32<true><<<gScore, thr>>>(q, k, sc, 128, HID, HID, 2048,
                                     SB, 128, SB, 128, 16 * SB, SB,
                                     0.08838834764831845f);

    // 5: softmax (+mask)
    softmax_kernel<<<32 * 2048, 256>>>(sc, mask);

    // 6: att = P @ V
    dim3 gPV(128 / BN, 2048 / BM, 32);
    gemm_tf32<false><<<gPV, thr>>>(sc, v, att, 2048, 2048, HID, HID,
                                   16 * SB, SB, SB, 128, SB, 128, 1.0f);

    // 7: out = att @ Wo^T
    gemm_tf32<true><<<gProj, thr>>>(att, Wo, out, HID, HID, HID, HID,
                                    0, 0, 0, 0, 0, 0, 1.0f);
}

// round 3
// speedup vs baseline: 2.9118x; 1.6219x over previous
#include <cuda_runtime.h>
#include <math.h>

// ---------------------------------------------------------------------------
// TensorParallelAttention — tf32 mma.sync, cp.async 2-stage pipeline,
// XOR-swizzled conflict-free smem.
// ---------------------------------------------------------------------------

#define BM 128
#define BN 128
#define BK 32

#define HID 2048
#define MROWS 4096
#define SB 4194304L

#define TILE_U32 4096           // 128*32 (or 32*128) u32 per stage
#define SMEM_BYTES (4 * TILE_U32 * 4)   // 2 stages x (A+B) = 64 KB

__device__ float g_q[MROWS * HID];
__device__ float g_k[MROWS * HID];
__device__ float g_v[MROWS * HID];
__device__ float g_att[MROWS * HID];
__device__ float g_scores[32L * SB];

__device__ __forceinline__ unsigned f2tf32(unsigned x) {
    unsigned u;
    asm("cvt.rna.tf32.f32 %0, %1;" : "=r"(u) : "f"(__uint_as_float(x)));
    return u;
}

__device__ __forceinline__ void cp_async16(unsigned* smem_dst, const void* gmem_src) {
    unsigned s = (unsigned)__cvta_generic_to_shared(smem_dst);
    asm volatile("cp.async.cg.shared.global [%0], [%1], 16;\n" :: "r"(s), "l"(gmem_src));
}
__device__ __forceinline__ void cp_commit() {
    asm volatile("cp.async.commit_group;\n");
}
template <int N> __device__ __forceinline__ void cp_wait() {
    asm volatile("cp.async.wait_group %0;\n" :: "n"(N));
}

// C[M,N] = alpha * A @ op(B); TRANS_B: B is [N,K] (k-contig), else [K,N].
template <bool TRANS_B>
__global__ __launch_bounds__(256, 2)
void gemm_tf32(const float* __restrict__ A, const float* __restrict__ B,
               float* __restrict__ C,
               int K, int lda, int ldb, int ldc,
               long sA1, long sA2, long sB1, long sB2, long sC1, long sC2,
               float alpha)
{
    extern __shared__ unsigned smem[];
    unsigned* AsBase = smem;                     // [2][128][32] swizzled
    unsigned* BsBase = smem + 2 * TILE_U32;      // [2][...] swizzled

    const int tid  = threadIdx.x;
    const int lane = tid & 31;
    const int wid  = tid >> 5;
    const int grp  = lane >> 2;     // 0..7
    const int tig  = lane & 3;      // 0..3

    const int wm = wid & 1;         // 2 warps along M -> 64 rows
    const int wn = wid >> 1;        // 4 warps along N -> 32 cols

    const long zb = (long)(blockIdx.z >> 4);
    const long zh = (long)(blockIdx.z & 15);
    A += zb * sA1 + zh * sA2;
    B += zb * sB1 + zh * sB2;
    C += zb * sC1 + zh * sC2;

    const int bm = blockIdx.y * BM;
    const int bn = blockIdx.x * BN;

    // per-thread copy coordinates
    const int ar  = tid >> 1;                  // reuse below per-chunk instead
    (void)ar;

    float acc[4][4][4];
#pragma unroll
    for (int i = 0; i < 4; i++)
#pragma unroll
        for (int j = 0; j < 4; j++)
#pragma unroll
            for (int t = 0; t < 4; t++) acc[i][j][t] = 0.0f;

    const int ntiles = K / BK;

    // ---- tile issue helper (inlined twice) ----
#define ISSUE_TILE(KT, STAGE)                                                   \
    do {                                                                        \
        unsigned* as = AsBase + (STAGE) * TILE_U32;                             \
        unsigned* bs = BsBase + (STAGE) * TILE_U32;                             \
        _Pragma("unroll")                                                       \
        for (int i = 0; i < 4; i++) {                                           \
            int linear = tid + i * 256;                                         \
            int r  = linear >> 3;                                               \
            int c4 = (linear & 7) * 4;                                          \
            cp_async16(&as[r * 32 + (c4 ^ ((r & 7) << 2))],                     \
                       &A[(long)(bm + r) * lda + ((KT) * BK + c4)]);            \
        }                                                                       \
        if (TRANS_B) {                                                          \
            _Pragma("unroll")                                                   \
            for (int i = 0; i < 4; i++) {                                       \
                int linear = tid + i * 256;                                     \
                int r  = linear >> 3;                                           \
                int c4 = (linear & 7) * 4;                                      \
                cp_async16(&bs[r * 32 + (c4 ^ ((r & 7) << 2))],                 \
                           &B[(long)(bn + r) * ldb + ((KT) * BK + c4)]);        \
            }                                                                   \
        } else {                                                                \
            _Pragma("unroll")                                                   \
            for (int i = 0; i < 4; i++) {                                       \
                int linear = tid + i * 256;                                     \
                int rb = linear >> 5;                                           \
                int cb = (linear & 31) * 4;                                     \
                cp_async16(&bs[rb * 128 + (cb ^ ((rb & 3) << 3))],              \
                           &B[(long)((KT) * BK + rb) * ldb + (bn + cb)]);       \
            }                                                                   \
        }                                                                       \
        cp_commit();                                                            \
    } while (0)

    ISSUE_TILE(0, 0);

    for (int kt = 0; kt < ntiles; kt++) {
        const int cur = kt & 1;
        if (kt + 1 < ntiles) {
            ISSUE_TILE(kt + 1, cur ^ 1);
            cp_wait<1>();
        } else {
            cp_wait<0>();
        }
        __syncthreads();

        const unsigned* as = AsBase + cur * TILE_U32;
        const unsigned* bs = BsBase + cur * TILE_U32;

#pragma unroll
        for (int kk = 0; kk < BK; kk += 8) {
            unsigned af[4][4], bf[4][2];
            const int k1 = kk + tig;
            const int k2 = kk + tig + 4;
#pragma unroll
            for (int mt = 0; mt < 4; mt++) {
                int m  = wm * 64 + mt * 16 + grp;
                int sw = (m & 7) << 2;
                af[mt][0] = f2tf32(as[m * 32 + (k1 ^ sw)]);
                af[mt][1] = f2tf32(as[(m + 8) * 32 + (k1 ^ sw)]);
                af[mt][2] = f2tf32(as[m * 32 + (k2 ^ sw)]);
                af[mt][3] = f2tf32(as[(m + 8) * 32 + (k2 ^ sw)]);
            }
#pragma unroll
            for (int nt = 0; nt < 4; nt++) {
                int n = wn * 32 + nt * 8 + grp;
                if (TRANS_B) {
                    int sw = (n & 7) << 2;
                    bf[nt][0] = f2tf32(bs[n * 32 + (k1 ^ sw)]);
                    bf[nt][1] = f2tf32(bs[n * 32 + (k2 ^ sw)]);
                } else {
                    int sw = tig << 3;          // (k1&3)==(k2&3)==tig
                    bf[nt][0] = f2tf32(bs[k1 * 128 + (n ^ sw)]);
                    bf[nt][1] = f2tf32(bs[k2 * 128 + (n ^ sw)]);
                }
            }
#pragma unroll
            for (int mt = 0; mt < 4; mt++)
#pragma unroll
                for (int nt = 0; nt < 4; nt++) {
                    asm volatile(
                        "mma.sync.aligned.m16n8k8.row.col.f32.tf32.tf32.f32 "
                        "{%0,%1,%2,%3}, {%4,%5,%6,%7}, {%8,%9}, {%0,%1,%2,%3};"
                        : "+f"(acc[mt][nt][0]), "+f"(acc[mt][nt][1]),
                          "+f"(acc[mt][nt][2]), "+f"(acc[mt][nt][3])
                        : "r"(af[mt][0]), "r"(af[mt][1]),
                          "r"(af[mt][2]), "r"(af[mt][3]),
                          "r"(bf[nt][0]), "r"(bf[nt][1]));
                }
        }
        __syncthreads();
    }
#undef ISSUE_TILE

    // ---- epilogue ----
#pragma unroll
    for (int mt = 0; mt < 4; mt++) {
        int r0 = bm + wm * 64 + mt * 16 + grp;
        int r1 = r0 + 8;
#pragma unroll
        for (int nt = 0; nt < 4; nt++) {
            int c = bn + wn * 32 + nt * 8 + tig * 2;
            float2 v0 = make_float2(acc[mt][nt][0] * alpha, acc[mt][nt][1] * alpha);
            float2 v1 = make_float2(acc[mt][nt][2] * alpha, acc[mt][nt][3] * alpha);
            *(float2*)&C[(long)r0 * ldc + c] = v0;
            *(float2*)&C[(long)r1 * ldc + c] = v1;
        }
    }
}

// In-place softmax over rows of g_scores; row = z*2048 + q, adds mask[q, :].
__global__ __launch_bounds__(256)
void softmax_kernel(float* __restrict__ S, const float* __restrict__ mask)
{
    __shared__ float red[8];
    const long row = blockIdx.x;
    const int  q   = (int)(row & 2047);
    float* p = S + row * 2048L;
    const float* mr = mask + (long)q * 2048L;

    const int tid  = threadIdx.x;
    const int lane = tid & 31;
    const int wid  = tid >> 5;

    float v[8];
    float4 a0 = ((const float4*)p)[tid];
    float4 a1 = ((const float4*)p)[tid + 256];
    float4 m0 = ((const float4*)mr)[tid];
    float4 m1 = ((const float4*)mr)[tid + 256];
    v[0] = a0.x + m0.x; v[1] = a0.y + m0.y; v[2] = a0.z + m0.z; v[3] = a0.w + m0.w;
    v[4] = a1.x + m1.x; v[5] = a1.y + m1.y; v[6] = a1.z + m1.z; v[7] = a1.w + m1.w;

    float mx = v[0];
#pragma unroll
    for (int i = 1; i < 8; i++) mx = fmaxf(mx, v[i]);
#pragma unroll
    for (int o = 16; o > 0; o >>= 1)
        mx = fmaxf(mx, __shfl_xor_sync(0xffffffffu, mx, o));
    if (lane == 0) red[wid] = mx;
    __syncthreads();
    mx = red[0];
#pragma unroll
    for (int i = 1; i < 8; i++) mx = fmaxf(mx, red[i]);
    __syncthreads();

    float s = 0.0f;
#pragma unroll
    for (int i = 0; i < 8; i++) { v[i] = __expf(v[i] - mx); s += v[i]; }
#pragma unroll
    for (int o = 16; o > 0; o >>= 1)
        s += __shfl_xor_sync(0xffffffffu, s, o);
    if (lane == 0) red[wid] = s;
    __syncthreads();
    s = red[0];
#pragma unroll
    for (int i = 1; i < 8; i++) s += red[i];

    float inv = 1.0f / s;
    ((float4*)p)[tid]       = make_float4(v[0] * inv, v[1] * inv, v[2] * inv, v[3] * inv);
    ((float4*)p)[tid + 256] = make_float4(v[4] * inv, v[5] * inv, v[6] * inv, v[7] * inv);
}

extern "C" void kernel_launch(void* const* d_in, const int* in_sizes, int n_in,
                              void* d_out, int out_size)
{
    (void)in_sizes; (void)n_in; (void)out_size;
    const float* hidden = (const float*)d_in[0];
    const float* mask   = (const float*)d_in[1];
    const float* Wq     = (const float*)d_in[2];
    const float* Wk     = (const float*)d_in[3];
    const float* Wv     = (const float*)d_in[4];
    const float* Wo     = (const float*)d_in[5];
    float* out = (float*)d_out;

    float *q, *k, *v, *att, *sc;
    cudaGetSymbolAddress((void**)&q,   g_q);
    cudaGetSymbolAddress((void**)&k,   g_k);
    cudaGetSymbolAddress((void**)&v,   g_v);
    cudaGetSymbolAddress((void**)&att, g_att);
    cudaGetSymbolAddress((void**)&sc,  g_scores);

    cudaFuncSetAttribute(gemm_tf32<true>,
                         cudaFuncAttributeMaxDynamicSharedMemorySize, SMEM_BYTES);
    cudaFuncSetAttribute(gemm_tf32<false>,
                         cudaFuncAttributeMaxDynamicSharedMemorySize, SMEM_BYTES);

    dim3 thr(256);

    // 1-3: Q/K/V projections
    dim3 gProj(HID / BN, MROWS / BM, 1);
    gemm_tf32<true><<<gProj, thr, SMEM_BYTES>>>(hidden, Wq, q, HID, HID, HID, HID,
                                                0, 0, 0, 0, 0, 0, 1.0f);
    gemm_tf32<true><<<gProj, thr, SMEM_BYTES>>>(hidden, Wk, k, HID, HID, HID, HID,
                                                0, 0, 0, 0, 0, 0, 1.0f);
    gemm_tf32<true><<<gProj, thr, SMEM_BYTES>>>(hidden, Wv, v, HID, HID, HID, HID,
                                                0, 0, 0, 0, 0, 0, 1.0f);

    // 4: scores = scale * Q @ K^T  (z = b*16 + h)
    dim3 gScore(2048 / BN, 2048 / BM, 32);
    gemm_tf32<true><<<gScore, thr, SMEM_BYTES>>>(q, k, sc, 128, HID, HID, 2048,
                                                 SB, 128, SB, 128, 16 * SB, SB,
                                                 0.08838834764831845f);

    // 5: softmax (+mask)
    softmax_kernel<<<32 * 2048, 256>>>(sc, mask);

    // 6: att = P @ V
    dim3 gPV(128 / BN, 2048 / BM, 32);
    gemm_tf32<false><<<gPV, thr, SMEM_BYTES>>>(sc, v, att, 2048, 2048, HID, HID,
                                               16 * SB, SB, SB, 128, SB, 128, 1.0f);

    // 7: out = att @ Wo^T
    gemm_tf32<true><<<gProj, thr, SMEM_BYTES>>>(att, Wo, out, HID, HID, HID, HID,
                                                0, 0, 0, 0, 0, 0, 1.0f);
}

// round 4
// speedup vs baseline: 4.4914x; 1.5425x over previous
#include <cuda_runtime.h>
#include <cuda_fp16.h>
#include <math.h>

// ---------------------------------------------------------------------------
// TensorParallelAttention — fp16 mma.sync m16n8k16, fp32 accumulate.
// All GEMM operands pre-converted to fp16 in gmem; cp.async 3-stage pipeline;
// stride-20 (80B) smem rows -> conflict-free scalar fragment LDS, no swizzle.
//   0.   convert hidden/Wq/Wk/Wv/Wo -> fp16
//   1-2. q16/k16 = h16 @ W^T            (fp16 out)
//   3.   vt16    = Wv16 @ h16^T         (V transposed: [dim][token])
//   4.   scores  = alpha * q16 @ k16^T  (fp32 out, batched z=32)
//   5.   softmax rows (+mask, fp32 math) -> p16
//   6.   att16   = p16 @ vt16^T         (batched z=32)
//   7.   out     = att16 @ Wo^T         (fp32 out)
// ---------------------------------------------------------------------------

#define BM 128
#define BN 128
#define BKH 32                 // k-extent per tile, in halves
#define ROW_U32 20             // 16 data u32 + 4 pad  (80B rows, bank-perfect)
#define STAGE_U32 (128 * ROW_U32)
#define NSTAGES 3
#define SMEM_BYTES16 (NSTAGES * 2 * STAGE_U32 * 4)   // 61440

#define HID 2048
#define MROWS 4096
#define SB 4194304L

__device__ __half g_h16[MROWS * HID];
__device__ __half g_wq16[HID * HID];
__device__ __half g_wk16[HID * HID];
__device__ __half g_wv16[HID * HID];
__device__ __half g_wo16[HID * HID];
__device__ __half g_q16[MROWS * HID];
__device__ __half g_k16[MROWS * HID];
__device__ __half g_vt16[MROWS * HID];
__device__ __half g_att16[MROWS * HID];
__device__ __half g_p16[32L * SB];
__device__ float  g_scores[32L * SB];

__device__ __forceinline__ void cp_async16(unsigned* smem_dst, const void* gmem_src) {
    unsigned s = (unsigned)__cvta_generic_to_shared(smem_dst);
    asm volatile("cp.async.cg.shared.global [%0], [%1], 16;\n" :: "r"(s), "l"(gmem_src));
}
__device__ __forceinline__ void cp_commit() {
    asm volatile("cp.async.commit_group;\n");
}
template <int N> __device__ __forceinline__ void cp_wait() {
    asm volatile("cp.async.wait_group %0;\n" :: "n"(N));
}

// C[M,N] = alpha * A @ B^T ; A:[M,K] k-contig fp16, B:[N,K] k-contig fp16.
// Batched via blockIdx.z (z = zb*16 + zh), element-unit strides.
template <typename OutT>
__global__ __launch_bounds__(256, 2)
void gemm_f16(const __half* __restrict__ A, const __half* __restrict__ B,
              OutT* __restrict__ C,
              int K, int lda, int ldb, int ldc,
              long sA1, long sA2, long sB1, long sB2, long sC1, long sC2,
              float alpha)
{
    extern __shared__ unsigned smem[];
    unsigned* AsBase = smem;
    unsigned* BsBase = smem + NSTAGES * STAGE_U32;

    const int tid  = threadIdx.x;
    const int lane = tid & 31;
    const int wid  = tid >> 5;
    const int grp  = lane >> 2;     // 0..7
    const int tig  = lane & 3;      // 0..3

    const int wm = wid & 1;         // 2 warps along M
    const int wn = wid >> 1;        // 4 warps along N

    const long zb = (long)(blockIdx.z >> 4);
    const long zh = (long)(blockIdx.z & 15);
    A += zb * sA1 + zh * sA2;
    B += zb * sB1 + zh * sB2;
    C += zb * sC1 + zh * sC2;

    const int bm = blockIdx.y * BM;
    const int bn = blockIdx.x * BN;

    float acc[4][4][4];
#pragma unroll
    for (int i = 0; i < 4; i++)
#pragma unroll
        for (int j = 0; j < 4; j++)
#pragma unroll
            for (int t = 0; t < 4; t++) acc[i][j][t] = 0.0f;

    const int ntiles = K / BKH;

    // copy coords: 512 16B chunks per operand per stage, 2 per thread
#define ISSUE_TILE(KT, STAGE)                                                   \
    do {                                                                        \
        unsigned* as = AsBase + (STAGE) * STAGE_U32;                            \
        unsigned* bs = BsBase + (STAGE) * STAGE_U32;                            \
        _Pragma("unroll")                                                       \
        for (int i = 0; i < 2; i++) {                                           \
            int linear = tid + i * 256;                                         \
            int r  = linear >> 2;                                               \
            int c4 = (linear & 3) << 2;     /* u32 col: 0,4,8,12 */             \
            cp_async16(&as[r * ROW_U32 + c4],                                   \
                       &A[(long)(bm + r) * lda + (KT) * BKH + c4 * 2]);         \
            cp_async16(&bs[r * ROW_U32 + c4],                                   \
                       &B[(long)(bn + r) * ldb + (KT) * BKH + c4 * 2]);         \
        }                                                                       \
        cp_commit();                                                            \
    } while (0)

    ISSUE_TILE(0, 0);
    if (ntiles > 1) ISSUE_TILE(1, 1);
    else cp_commit();   // keep group count consistent

    for (int kt = 0; kt < ntiles; kt++) {
        const int cur = kt % NSTAGES;
        if (kt + 2 < ntiles) {
            ISSUE_TILE(kt + 2, (kt + 2) % NSTAGES);
            cp_wait<2>();
        } else if (kt + 1 < ntiles) {
            cp_wait<1>();
        } else {
            cp_wait<0>();
        }
        __syncthreads();

        const unsigned* as = AsBase + cur * STAGE_U32;
        const unsigned* bs = BsBase + cur * STAGE_U32;

#pragma unroll
        for (int s = 0; s < 2; s++) {       // two k16 steps per tile
            unsigned af[4][4], bf[4][2];
            const int p0 = s * 8 + tig;     // k-pair index (u32 col)
#pragma unroll
            for (int mt = 0; mt < 4; mt++) {
                int m = wm * 64 + mt * 16 + grp;
                af[mt][0] = as[m * ROW_U32 + p0];
                af[mt][1] = as[(m + 8) * ROW_U32 + p0];
                af[mt][2] = as[m * ROW_U32 + p0 + 4];
                af[mt][3] = as[(m + 8) * ROW_U32 + p0 + 4];
            }
#pragma unroll
            for (int nt = 0; nt < 4; nt++) {
                int n = wn * 32 + nt * 8 + grp;
                bf[nt][0] = bs[n * ROW_U32 + p0];
                bf[nt][1] = bs[n * ROW_U32 + p0 + 4];
            }
#pragma unroll
            for (int mt = 0; mt < 4; mt++)
#pragma unroll
                for (int nt = 0; nt < 4; nt++) {
                    asm volatile(
                        "mma.sync.aligned.m16n8k16.row.col.f32.f16.f16.f32 "
                        "{%0,%1,%2,%3}, {%4,%5,%6,%7}, {%8,%9}, {%0,%1,%2,%3};"
                        : "+f"(acc[mt][nt][0]), "+f"(acc[mt][nt][1]),
                          "+f"(acc[mt][nt][2]), "+f"(acc[mt][nt][3])
                        : "r"(af[mt][0]), "r"(af[mt][1]),
                          "r"(af[mt][2]), "r"(af[mt][3]),
                          "r"(bf[nt][0]), "r"(bf[nt][1]));
                }
        }
        __syncthreads();
    }
#undef ISSUE_TILE

    // ---- epilogue ----
#pragma unroll
    for (int mt = 0; mt < 4; mt++) {
        int r0 = bm + wm * 64 + mt * 16 + grp;
        int r1 = r0 + 8;
#pragma unroll
        for (int nt = 0; nt < 4; nt++) {
            int c = bn + wn * 32 + nt * 8 + tig * 2;
            float x0 = acc[mt][nt][0] * alpha, x1 = acc[mt][nt][1] * alpha;
            float x2 = acc[mt][nt][2] * alpha, x3 = acc[mt][nt][3] * alpha;
            if (sizeof(OutT) == 2) {
                *(__half2*)&((__half*)C)[(long)r0 * ldc + c] = __floats2half2_rn(x0, x1);
                *(__half2*)&((__half*)C)[(long)r1 * ldc + c] = __floats2half2_rn(x2, x3);
            } else {
                *(float2*)&((float*)C)[(long)r0 * ldc + c] = make_float2(x0, x1);
                *(float2*)&((float*)C)[(long)r1 * ldc + c] = make_float2(x2, x3);
            }
        }
    }
}

// fp32 -> fp16 elementwise (n multiple of 4)
__global__ void f2h_kernel(const float* __restrict__ in, __half* __restrict__ out, long n)
{
    long i = ((long)blockIdx.x * blockDim.x + threadIdx.x) * 4;
    if (i < n) {
        float4 v = *(const float4*)&in[i];
        *(__half2*)&out[i]     = __floats2half2_rn(v.x, v.y);
        *(__half2*)&out[i + 2] = __floats2half2_rn(v.z, v.w);
    }
}

// softmax over rows of g_scores (fp32), +mask, write fp16 P.
__global__ __launch_bounds__(256)
void softmax_kernel(const float* __restrict__ S, const float* __restrict__ mask,
                    __half* __restrict__ P)
{
    __shared__ float red[8];
    const long row = blockIdx.x;
    const int  q   = (int)(row & 2047);
    const float* p = S + row * 2048L;
    const float* mr = mask + (long)q * 2048L;
    __half* po = P + row * 2048L;

    const int tid  = threadIdx.x;
    const int lane = tid & 31;
    const int wid  = tid >> 5;

    float v[8];
    float4 a0 = ((const float4*)p)[tid];
    float4 a1 = ((const float4*)p)[tid + 256];
    float4 m0 = ((const float4*)mr)[tid];
    float4 m1 = ((const float4*)mr)[tid + 256];
    v[0] = a0.x + m0.x; v[1] = a0.y + m0.y; v[2] = a0.z + m0.z; v[3] = a0.w + m0.w;
    v[4] = a1.x + m1.x; v[5] = a1.y + m1.y; v[6] = a1.z + m1.z; v[7] = a1.w + m1.w;

    float mx = v[0];
#pragma unroll
    for (int i = 1; i < 8; i++) mx = fmaxf(mx, v[i]);
#pragma unroll
    for (int o = 16; o > 0; o >>= 1)
        mx = fmaxf(mx, __shfl_xor_sync(0xffffffffu, mx, o));
    if (lane == 0) red[wid] = mx;
    __syncthreads();
    mx = red[0];
#pragma unroll
    for (int i = 1; i < 8; i++) mx = fmaxf(mx, red[i]);
    __syncthreads();

    float s = 0.0f;
#pragma unroll
    for (int i = 0; i < 8; i++) { v[i] = __expf(v[i] - mx); s += v[i]; }
#pragma unroll
    for (int o = 16; o > 0; o >>= 1)
        s += __shfl_xor_sync(0xffffffffu, s, o);
    if (lane == 0) red[wid] = s;
    __syncthreads();
    s = red[0];
#pragma unroll
    for (int i = 1; i < 8; i++) s += red[i];

    float inv = 1.0f / s;
    *(__half2*)&po[tid * 4 + 0]        = __floats2half2_rn(v[0] * inv, v[1] * inv);
    *(__half2*)&po[tid * 4 + 2]        = __floats2half2_rn(v[2] * inv, v[3] * inv);
    *(__half2*)&po[1024 + tid * 4 + 0] = __floats2half2_rn(v[4] * inv, v[5] * inv);
    *(__half2*)&po[1024 + tid * 4 + 2] = __floats2half2_rn(v[6] * inv, v[7] * inv);
}

extern "C" void kernel_launch(void* const* d_in, const int* in_sizes, int n_in,
                              void* d_out, int out_size)
{
    (void)in_sizes; (void)n_in; (void)out_size;
    const float* hidden = (const float*)d_in[0];
    const float* mask   = (const float*)d_in[1];
    const float* Wq     = (const float*)d_in[2];
    const float* Wk     = (const float*)d_in[3];
    const float* Wv     = (const float*)d_in[4];
    const float* Wo     = (const float*)d_in[5];
    float* out = (float*)d_out;

    __half *h16, *wq16, *wk16, *wv16, *wo16, *q16, *k16, *vt16, *att16, *p16;
    float *sc;
    cudaGetSymbolAddress((void**)&h16,  g_h16);
    cudaGetSymbolAddress((void**)&wq16, g_wq16);
    cudaGetSymbolAddress((void**)&wk16, g_wk16);
    cudaGetSymbolAddress((void**)&wv16, g_wv16);
    cudaGetSymbolAddress((void**)&wo16, g_wo16);
    cudaGetSymbolAddress((void**)&q16,  g_q16);
    cudaGetSymbolAddress((void**)&k16,  g_k16);
    cudaGetSymbolAddress((void**)&vt16, g_vt16);
    cudaGetSymbolAddress((void**)&att16, g_att16);
    cudaGetSymbolAddress((void**)&p16,  g_p16);
    cudaGetSymbolAddress((void**)&sc,   g_scores);

    cudaFuncSetAttribute(gemm_f16<__half>,
                         cudaFuncAttributeMaxDynamicSharedMemorySize, SMEM_BYTES16);
    cudaFuncSetAttribute(gemm_f16<float>,
                         cudaFuncAttributeMaxDynamicSharedMemorySize, SMEM_BYTES16);

    dim3 thr(256);

    // 0: convert inputs to fp16
    f2h_kernel<<<(MROWS * HID) / 1024, 256>>>(hidden, h16, (long)MROWS * HID);
    f2h_kernel<<<(HID * HID) / 1024, 256>>>(Wq, wq16, (long)HID * HID);
    f2h_kernel<<<(HID * HID) / 1024, 256>>>(Wk, wk16, (long)HID * HID);
    f2h_kernel<<<(HID * HID) / 1024, 256>>>(Wv, wv16, (long)HID * HID);
    f2h_kernel<<<(HID * HID) / 1024, 256>>>(Wo, wo16, (long)HID * HID);

    // 1-2: q16/k16 = h16 @ W^T   [4096 x 2048]
    dim3 gProj(HID / BN, MROWS / BM, 1);
    gemm_f16<__half><<<gProj, thr, SMEM_BYTES16>>>(h16, wq16, q16, HID, HID, HID, HID,
                                                   0, 0, 0, 0, 0, 0, 1.0f);
    gemm_f16<__half><<<gProj, thr, SMEM_BYTES16>>>(h16, wk16, k16, HID, HID, HID, HID,
                                                   0, 0, 0, 0, 0, 0, 1.0f);

    // 3: vt16 = Wv16 @ h16^T  -> [2048 dims x 4096 tokens]
    dim3 gVt(MROWS / BN, HID / BM, 1);
    gemm_f16<__half><<<gVt, thr, SMEM_BYTES16>>>(wv16, h16, vt16, HID, HID, HID, MROWS,
                                                 0, 0, 0, 0, 0, 0, 1.0f);

    // 4: scores = alpha * q @ k^T per z  (fp32 out)
    dim3 gScore(2048 / BN, 2048 / BM, 32);
    gemm_f16<float><<<gScore, thr, SMEM_BYTES16>>>(q16, k16, sc, 128, HID, HID, 2048,
                                                   SB, 128, SB, 128, 16 * SB, SB,
                                                   0.08838834764831845f);

    // 5: softmax (+mask) -> p16
    softmax_kernel<<<32 * 2048, 256>>>(sc, mask, p16);

    // 6: att16 = p16 @ vt16^T per z   (M=2048, N=128, K=2048)
    dim3 gPV(128 / BN, 2048 / BM, 32);
    gemm_f16<__half><<<gPV, thr, SMEM_BYTES16>>>(p16, vt16, att16, 2048, 2048, MROWS, HID,
                                                 16 * SB, SB, 2048, 128L * MROWS,
                                                 SB, 128, 1.0f);

    // 7: out = att16 @ Wo^T  (fp32 out)
    gemm_f16<float><<<gProj, thr, SMEM_BYTES16>>>(att16, wo16, out, HID, HID, HID, HID,
                                                  0, 0, 0, 0, 0, 0, 1.0f);
}

// round 5
// speedup vs baseline: 5.0097x; 1.1154x over previous
#include <cuda_runtime.h>
#include <cuda_fp16.h>
#include <math.h>

// ---------------------------------------------------------------------------
// TensorParallelAttention — fp16 mma + fused flash attention.
//   0.   convert hidden/W* -> fp16
//   1-2. q16/k16 = h16 @ W^T
//   3.   vt16    = Wv16 @ h16^T        (V transposed: [dim][token])
//   4.   flash:  att16 = softmax(alpha*q k^T + mask) @ v   (fused, per z)
//   5.   out     = att16 @ Wo^T        (fp32 out)
// ---------------------------------------------------------------------------

#define BM 128
#define BN 128
#define BKH 32
#define ROW_U32 20
#define STAGE_U32 (128 * ROW_U32)
#define NSTAGES 3
#define SMEM_BYTES16 (NSTAGES * 2 * STAGE_U32 * 4)

#define HID 2048
#define MROWS 4096

// flash tile constants
#define VROW 68                      // 64 data u32 + 4 pad per 128-half row
#define TSTAGE (128 * VROW)          // u32 per 128x128-half tile
#define FLASH_SMEM (5 * TSTAGE * 4)  // Q + 2xK + 2xV = 174080 B

__device__ __half g_h16[MROWS * HID];
__device__ __half g_wq16[HID * HID];
__device__ __half g_wk16[HID * HID];
__device__ __half g_wv16[HID * HID];
__device__ __half g_wo16[HID * HID];
__device__ __half g_q16[MROWS * HID];
__device__ __half g_k16[MROWS * HID];
__device__ __half g_vt16[MROWS * HID];
__device__ __half g_att16[MROWS * HID];

__device__ __forceinline__ void cp_async16(unsigned* smem_dst, const void* gmem_src) {
    unsigned s = (unsigned)__cvta_generic_to_shared(smem_dst);
    asm volatile("cp.async.cg.shared.global [%0], [%1], 16;\n" :: "r"(s), "l"(gmem_src));
}
__device__ __forceinline__ void cp_commit() {
    asm volatile("cp.async.commit_group;\n");
}
template <int N> __device__ __forceinline__ void cp_wait() {
    asm volatile("cp.async.wait_group %0;\n" :: "n"(N));
}
__device__ __forceinline__ unsigned packh2(float a, float b) {
    __half2 h = __floats2half2_rn(a, b);
    return *(unsigned*)&h;
}

// ---------------- generic fp16 GEMM (unchanged from R4) --------------------
template <typename OutT>
__global__ __launch_bounds__(256, 2)
void gemm_f16(const __half* __restrict__ A, const __half* __restrict__ B,
              OutT* __restrict__ C,
              int K, int lda, int ldb, int ldc,
              long sA1, long sA2, long sB1, long sB2, long sC1, long sC2,
              float alpha)
{
    extern __shared__ unsigned smem[];
    unsigned* AsBase = smem;
    unsigned* BsBase = smem + NSTAGES * STAGE_U32;

    const int tid  = threadIdx.x;
    const int lane = tid & 31;
    const int wid  = tid >> 5;
    const int grp  = lane >> 2;
    const int tig  = lane & 3;
    const int wm = wid & 1;
    const int wn = wid >> 1;

    const long zb = (long)(blockIdx.z >> 4);
    const long zh = (long)(blockIdx.z & 15);
    A += zb * sA1 + zh * sA2;
    B += zb * sB1 + zh * sB2;
    C += zb * sC1 + zh * sC2;

    const int bm = blockIdx.y * BM;
    const int bn = blockIdx.x * BN;

    float acc[4][4][4];
#pragma unroll
    for (int i = 0; i < 4; i++)
#pragma unroll
        for (int j = 0; j < 4; j++)
#pragma unroll
            for (int t = 0; t < 4; t++) acc[i][j][t] = 0.0f;

    const int ntiles = K / BKH;

#define ISSUE_TILE(KT, STAGE)                                                   \
    do {                                                                        \
        unsigned* as = AsBase + (STAGE) * STAGE_U32;                            \
        unsigned* bs = BsBase + (STAGE) * STAGE_U32;                            \
        _Pragma("unroll")                                                       \
        for (int i = 0; i < 2; i++) {                                           \
            int linear = tid + i * 256;                                         \
            int r  = linear >> 2;                                               \
            int c4 = (linear & 3) << 2;                                         \
            cp_async16(&as[r * ROW_U32 + c4],                                   \
                       &A[(long)(bm + r) * lda + (KT) * BKH + c4 * 2]);         \
            cp_async16(&bs[r * ROW_U32 + c4],                                   \
                       &B[(long)(bn + r) * ldb + (KT) * BKH + c4 * 2]);         \
        }                                                                       \
        cp_commit();                                                            \
    } while (0)

    ISSUE_TILE(0, 0);
    if (ntiles > 1) ISSUE_TILE(1, 1);
    else cp_commit();

    for (int kt = 0; kt < ntiles; kt++) {
        const int cur = kt % NSTAGES;
        if (kt + 2 < ntiles) {
            ISSUE_TILE(kt + 2, (kt + 2) % NSTAGES);
            cp_wait<2>();
        } else if (kt + 1 < ntiles) {
            cp_wait<1>();
        } else {
            cp_wait<0>();
        }
        __syncthreads();

        const unsigned* as = AsBase + cur * STAGE_U32;
        const unsigned* bs = BsBase + cur * STAGE_U32;

#pragma unroll
        for (int s = 0; s < 2; s++) {
            unsigned af[4][4], bf[4][2];
            const int p0 = s * 8 + tig;
#pragma unroll
            for (int mt = 0; mt < 4; mt++) {
                int m = wm * 64 + mt * 16 + grp;
                af[mt][0] = as[m * ROW_U32 + p0];
                af[mt][1] = as[(m + 8) * ROW_U32 + p0];
                af[mt][2] = as[m * ROW_U32 + p0 + 4];
                af[mt][3] = as[(m + 8) * ROW_U32 + p0 + 4];
            }
#pragma unroll
            for (int nt = 0; nt < 4; nt++) {
                int n = wn * 32 + nt * 8 + grp;
                bf[nt][0] = bs[n * ROW_U32 + p0];
                bf[nt][1] = bs[n * ROW_U32 + p0 + 4];
            }
#pragma unroll
            for (int mt = 0; mt < 4; mt++)
#pragma unroll
                for (int nt = 0; nt < 4; nt++) {
                    asm volatile(
                        "mma.sync.aligned.m16n8k16.row.col.f32.f16.f16.f32 "
                        "{%0,%1,%2,%3}, {%4,%5,%6,%7}, {%8,%9}, {%0,%1,%2,%3};"
                        : "+f"(acc[mt][nt][0]), "+f"(acc[mt][nt][1]),
                          "+f"(acc[mt][nt][2]), "+f"(acc[mt][nt][3])
                        : "r"(af[mt][0]), "r"(af[mt][1]),
                          "r"(af[mt][2]), "r"(af[mt][3]),
                          "r"(bf[nt][0]), "r"(bf[nt][1]));
                }
        }
        __syncthreads();
    }
#undef ISSUE_TILE

#pragma unroll
    for (int mt = 0; mt < 4; mt++) {
        int r0 = bm + wm * 64 + mt * 16 + grp;
        int r1 = r0 + 8;
#pragma unroll
        for (int nt = 0; nt < 4; nt++) {
            int c = bn + wn * 32 + nt * 8 + tig * 2;
            float x0 = acc[mt][nt][0] * alpha, x1 = acc[mt][nt][1] * alpha;
            float x2 = acc[mt][nt][2] * alpha, x3 = acc[mt][nt][3] * alpha;
            if (sizeof(OutT) == 2) {
                *(unsigned*)&((__half*)C)[(long)r0 * ldc + c] = packh2(x0, x1);
                *(unsigned*)&((__half*)C)[(long)r1 * ldc + c] = packh2(x2, x3);
            } else {
                *(float2*)&((float*)C)[(long)r0 * ldc + c] = make_float2(x0, x1);
                *(float2*)&((float*)C)[(long)r1 * ldc + c] = make_float2(x2, x3);
            }
        }
    }
}

// ---------------- fused flash attention ------------------------------------
// Grid: (16 q-tiles, 32 z). Block 256 (8 warps x 16 q-rows each).
// Q,K: [token][2048] fp16 (head cols h*128). Vt: [dim][token] fp16.
// att16 out: [token][2048] fp16.
__global__ __launch_bounds__(256, 1)
void flash_kernel(const __half* __restrict__ Q, const __half* __restrict__ K,
                  const __half* __restrict__ Vt, const float* __restrict__ mask,
                  __half* __restrict__ O)
{
    extern __shared__ unsigned sm[];
    unsigned* Qs = sm;                  // 128 x VROW
    unsigned* Ks = sm + TSTAGE;         // 2 stages
    unsigned* Vs = sm + 3 * TSTAGE;     // 2 stages

    const int tid  = threadIdx.x;
    const int lane = tid & 31;
    const int wq   = tid >> 5;          // warp -> 16-row band
    const int grp  = lane >> 2;
    const int tig  = lane & 3;

    const int z  = blockIdx.y;
    const int b  = z >> 4;
    const int h  = z & 15;
    const int qt = blockIdx.x;

    const __half* Qg = Q  + (long)(b * 2048 + qt * 128) * HID + h * 128;
    const __half* Kg = K  + (long)(b * 2048) * HID + h * 128;
    const __half* Vg = Vt + (long)(h * 128) * (long)MROWS + b * 2048;
    const float*  Mg = mask + (long)(qt * 128) * 2048;

#define ISSUE_KV(KT, STAGE)                                                     \
    do {                                                                        \
        unsigned* ks = Ks + (STAGE) * TSTAGE;                                   \
        unsigned* vs = Vs + (STAGE) * TSTAGE;                                   \
        _Pragma("unroll")                                                       \
        for (int i = 0; i < 8; i++) {                                           \
            int linear = tid + i * 256;                                         \
            int r  = linear >> 4;                                               \
            int c4 = (linear & 15) << 2;                                        \
            cp_async16(&ks[r * VROW + c4],                                      \
                       Kg + (long)((KT) * 128 + r) * HID + c4 * 2);             \
            cp_async16(&vs[r * VROW + c4],                                      \
                       Vg + (long)r * MROWS + (KT) * 128 + c4 * 2);             \
        }                                                                       \
        cp_commit();                                                            \
    } while (0)

    // group 0: Q + KV tile 0 ; group 1: KV tile 1
#pragma unroll
    for (int i = 0; i < 8; i++) {
        int linear = tid + i * 256;
        int r  = linear >> 4;
        int c4 = (linear & 15) << 2;
        cp_async16(&Qs[r * VROW + c4], Qg + (long)r * HID + c4 * 2);
    }
    ISSUE_KV(0, 0);
    ISSUE_KV(1, 1);

    float acc_o[16][4];
#pragma unroll
    for (int i = 0; i < 16; i++)
#pragma unroll
        for (int t = 0; t < 4; t++) acc_o[i][t] = 0.0f;
    float m0 = -1e30f, m1 = -1e30f, l0 = 0.0f, l1 = 0.0f;
    unsigned qf[8][4];

    const float alpha = 0.08838834764831845f;

    for (int kt = 0; kt < 16; kt++) {
        const int cur = kt & 1;
        if (kt + 1 < 16) cp_wait<1>(); else cp_wait<0>();
        __syncthreads();

        if (kt == 0) {
#pragma unroll
            for (int ks = 0; ks < 8; ks++) {
                int m = wq * 16 + grp;
                qf[ks][0] = Qs[m * VROW + ks * 8 + tig];
                qf[ks][1] = Qs[(m + 8) * VROW + ks * 8 + tig];
                qf[ks][2] = Qs[m * VROW + ks * 8 + tig + 4];
                qf[ks][3] = Qs[(m + 8) * VROW + ks * 8 + tig + 4];
            }
        }

        // ---- S = Q K^T ----
        float s[16][4];
#pragma unroll
        for (int nt = 0; nt < 16; nt++)
#pragma unroll
            for (int t = 0; t < 4; t++) s[nt][t] = 0.0f;

        const unsigned* ksm = Ks + cur * TSTAGE;
#pragma unroll
        for (int nt = 0; nt < 16; nt++) {
#pragma unroll
            for (int ks = 0; ks < 8; ks++) {
                unsigned b0 = ksm[(nt * 8 + grp) * VROW + ks * 8 + tig];
                unsigned b1 = ksm[(nt * 8 + grp) * VROW + ks * 8 + tig + 4];
                asm volatile(
                    "mma.sync.aligned.m16n8k16.row.col.f32.f16.f16.f32 "
                    "{%0,%1,%2,%3}, {%4,%5,%6,%7}, {%8,%9}, {%0,%1,%2,%3};"
                    : "+f"(s[nt][0]), "+f"(s[nt][1]), "+f"(s[nt][2]), "+f"(s[nt][3])
                    : "r"(qf[ks][0]), "r"(qf[ks][1]), "r"(qf[ks][2]), "r"(qf[ks][3]),
                      "r"(b0), "r"(b1));
            }
        }

        // ---- scale + mask + online softmax ----
        const int qr0 = wq * 16 + grp;
        float mn0 = m0, mn1 = m1;
#pragma unroll
        for (int nt = 0; nt < 16; nt++) {
            int kc = kt * 128 + nt * 8 + tig * 2;
            float2 mk0 = *(const float2*)&Mg[(long)qr0 * 2048 + kc];
            float2 mk1 = *(const float2*)&Mg[(long)(qr0 + 8) * 2048 + kc];
            s[nt][0] = s[nt][0] * alpha + mk0.x;
            s[nt][1] = s[nt][1] * alpha + mk0.y;
            s[nt][2] = s[nt][2] * alpha + mk1.x;
            s[nt][3] = s[nt][3] * alpha + mk1.y;
            mn0 = fmaxf(mn0, fmaxf(s[nt][0], s[nt][1]));
            mn1 = fmaxf(mn1, fmaxf(s[nt][2], s[nt][3]));
        }
        mn0 = fmaxf(mn0, __shfl_xor_sync(0xffffffffu, mn0, 1));
        mn0 = fmaxf(mn0, __shfl_xor_sync(0xffffffffu, mn0, 2));
        mn1 = fmaxf(mn1, __shfl_xor_sync(0xffffffffu, mn1, 1));
        mn1 = fmaxf(mn1, __shfl_xor_sync(0xffffffffu, mn1, 2));

        float c0 = __expf(m0 - mn0);
        float c1 = __expf(m1 - mn1);
        m0 = mn0; m1 = mn1;

        unsigned pf[16][2];
        float ls0 = 0.0f, ls1 = 0.0f;
#pragma unroll
        for (int nt = 0; nt < 16; nt++) {
            float e0 = __expf(s[nt][0] - mn0);
            float e1 = __expf(s[nt][1] - mn0);
            float e2 = __expf(s[nt][2] - mn1);
            float e3 = __expf(s[nt][3] - mn1);
            ls0 += e0 + e1; ls1 += e2 + e3;
            pf[nt][0] = packh2(e0, e1);
            pf[nt][1] = packh2(e2, e3);
        }
        ls0 += __shfl_xor_sync(0xffffffffu, ls0, 1);
        ls0 += __shfl_xor_sync(0xffffffffu, ls0, 2);
        ls1 += __shfl_xor_sync(0xffffffffu, ls1, 1);
        ls1 += __shfl_xor_sync(0xffffffffu, ls1, 2);
        l0 = c0 * l0 + ls0;
        l1 = c1 * l1 + ls1;

#pragma unroll
        for (int dn = 0; dn < 16; dn++) {
            acc_o[dn][0] *= c0; acc_o[dn][1] *= c0;
            acc_o[dn][2] *= c1; acc_o[dn][3] *= c1;
        }

        // ---- O += P V  (k-dim = keys) ----
        const unsigned* vsm = Vs + cur * TSTAGE;
#pragma unroll
        for (int dn = 0; dn < 16; dn++) {
#pragma unroll
            for (int kp = 0; kp < 8; kp++) {
                unsigned vb0 = vsm[(dn * 8 + grp) * VROW + kp * 8 + tig];
                unsigned vb1 = vsm[(dn * 8 + grp) * VROW + kp * 8 + tig + 4];
                asm volatile(
                    "mma.sync.aligned.m16n8k16.row.col.f32.f16.f16.f32 "
                    "{%0,%1,%2,%3}, {%4,%5,%6,%7}, {%8,%9}, {%0,%1,%2,%3};"
                    : "+f"(acc_o[dn][0]), "+f"(acc_o[dn][1]),
                      "+f"(acc_o[dn][2]), "+f"(acc_o[dn][3])
                    : "r"(pf[2 * kp][0]), "r"(pf[2 * kp][1]),
                      "r"(pf[2 * kp + 1][0]), "r"(pf[2 * kp + 1][1]),
                      "r"(vb0), "r"(vb1));
            }
        }

        __syncthreads();
        if (kt + 2 < 16) ISSUE_KV(kt + 2, cur);
    }
#undef ISSUE_KV

    // ---- epilogue ----
    float inv0 = 1.0f / l0;
    float inv1 = 1.0f / l1;
    long t0 = (long)(b * 2048 + qt * 128 + wq * 16 + grp);
    long t1 = t0 + 8;
#pragma unroll
    for (int dn = 0; dn < 16; dn++) {
        int col = h * 128 + dn * 8 + tig * 2;
        *(unsigned*)&O[t0 * HID + col] = packh2(acc_o[dn][0] * inv0, acc_o[dn][1] * inv0);
        *(unsigned*)&O[t1 * HID + col] = packh2(acc_o[dn][2] * inv1, acc_o[dn][3] * inv1);
    }
}

// fp32 -> fp16 elementwise (n multiple of 4)
__global__ void f2h_kernel(const float* __restrict__ in, __half* __restrict__ out, long n)
{
    long i = ((long)blockIdx.x * blockDim.x + threadIdx.x) * 4;
    if (i < n) {
        float4 v = *(const float4*)&in[i];
        *(__half2*)&out[i]     = __floats2half2_rn(v.x, v.y);
        *(__half2*)&out[i + 2] = __floats2half2_rn(v.z, v.w);
    }
}

extern "C" void kernel_launch(void* const* d_in, const int* in_sizes, int n_in,
                              void* d_out, int out_size)
{
    (void)in_sizes; (void)n_in; (void)out_size;
    const float* hidden = (const float*)d_in[0];
    const float* mask   = (const float*)d_in[1];
    const float* Wq     = (const float*)d_in[2];
    const float* Wk     = (const float*)d_in[3];
    const float* Wv     = (const float*)d_in[4];
    const float* Wo     = (const float*)d_in[5];
    float* out = (float*)d_out;

    __half *h16, *wq16, *wk16, *wv16, *wo16, *q16, *k16, *vt16, *att16;
    cudaGetSymbolAddress((void**)&h16,   g_h16);
    cudaGetSymbolAddress((void**)&wq16,  g_wq16);
    cudaGetSymbolAddress((void**)&wk16,  g_wk16);
    cudaGetSymbolAddress((void**)&wv16,  g_wv16);
    cudaGetSymbolAddress((void**)&wo16,  g_wo16);
    cudaGetSymbolAddress((void**)&q16,   g_q16);
    cudaGetSymbolAddress((void**)&k16,   g_k16);
    cudaGetSymbolAddress((void**)&vt16,  g_vt16);
    cudaGetSymbolAddress((void**)&att16, g_att16);

    cudaFuncSetAttribute(gemm_f16<__half>,
                         cudaFuncAttributeMaxDynamicSharedMemorySize, SMEM_BYTES16);
    cudaFuncSetAttribute(gemm_f16<float>,
                         cudaFuncAttributeMaxDynamicSharedMemorySize, SMEM_BYTES16);
    cudaFuncSetAttribute(flash_kernel,
                         cudaFuncAttributeMaxDynamicSharedMemorySize, FLASH_SMEM);

    dim3 thr(256);

    // 0: convert to fp16
    f2h_kernel<<<(MROWS * HID) / 1024, 256>>>(hidden, h16, (long)MROWS * HID);
    f2h_kernel<<<(HID * HID) / 1024, 256>>>(Wq, wq16, (long)HID * HID);
    f2h_kernel<<<(HID * HID) / 1024, 256>>>(Wk, wk16, (long)HID * HID);
    f2h_kernel<<<(HID * HID) / 1024, 256>>>(Wv, wv16, (long)HID * HID);
    f2h_kernel<<<(HID * HID) / 1024, 256>>>(Wo, wo16, (long)HID * HID);

    // 1-2: Q/K projections
    dim3 gProj(HID / BN, MROWS / BM, 1);
    gemm_f16<__half><<<gProj, thr, SMEM_BYTES16>>>(h16, wq16, q16, HID, HID, HID, HID,
                                                   0, 0, 0, 0, 0, 0, 1.0f);
    gemm_f16<__half><<<gProj, thr, SMEM_BYTES16>>>(h16, wk16, k16, HID, HID, HID, HID,
                                                   0, 0, 0, 0, 0, 0, 1.0f);

    // 3: vt16 = Wv16 @ h16^T  -> [2048 dims][4096 tokens]
    dim3 gVt(MROWS / BN, HID / BM, 1);
    gemm_f16<__half><<<gVt, thr, SMEM_BYTES16>>>(wv16, h16, vt16, HID, HID, HID, MROWS,
                                                 0, 0, 0, 0, 0, 0, 1.0f);

    // 4: fused attention
    dim3 gFlash(16, 32, 1);
    flash_kernel<<<gFlash, thr, FLASH_SMEM>>>(q16, k16, vt16, mask, att16);

    // 5: out = att16 @ Wo^T
    gemm_f16<float><<<gProj, thr, SMEM_BYTES16>>>(att16, wo16, out, HID, HID, HID, HID,
                                                  0, 0, 0, 0, 0, 0, 1.0f);
}

// round 7
// speedup vs baseline: 5.2663x; 1.0512x over previous
#include <cuda_runtime.h>
#include <cuda_fp16.h>
#include <math.h>

// ---------------------------------------------------------------------------
// TensorParallelAttention — fp16 mma.sync (legacy HMMA; tcgen05 not emittable
// by this harness' PTX target) + fused flash attention at 2 CTAs/SM.
//   0.   convert hidden -> h16; Wq|Wk -> wqk16 (concat); Wv -> wv16; Wo -> wo16
//   1.   qk16 = h16 @ [Wq|Wk]^T          (one GEMM, N=4096, ldc=4096)
//   2.   vt16 = Wv16 @ h16^T             (V transposed: [dim][token])
//   3.   flash: att16 = softmax(aQK^T+M)V   (64q x 64k tiles, 2 CTA/SM)
//   4.   out  = att16 @ Wo^T             (fp32 out)
// ---------------------------------------------------------------------------

#define BM 128
#define BN 128
#define ROW_U32 20
#define STAGE_U32 (128 * ROW_U32)
#define NSTAGES 3
#define SMEM_BYTES16 (NSTAGES * 2 * STAGE_U32 * 4)

#define HID 2048
#define MROWS 4096
#define QKLD 4096                     // ld of concatenated QK output

// ---- flash tiles: 64 q-rows, 64-key K/V tiles, 128 threads, 2 CTA/SM ----
#define KROW 68                       // K/Q row stride in u32 (64 data + 4 pad)
#define VROWU 36                      // V row stride in u32 (32 data + 4 pad)
#define QS_U32 (64 * KROW)            // 4352
#define KS_U32 (64 * KROW)            // 4352 per stage
#define VS_U32 (128 * VROWU)          // 4608 per stage
#define FLASH_SMEM ((QS_U32 + 2 * KS_U32 + 2 * VS_U32) * 4)   // 89088

__device__ __half g_h16[MROWS * HID];
__device__ __half g_wqk16[2L * HID * HID];
__device__ __half g_wv16[HID * HID];
__device__ __half g_wo16[HID * HID];
__device__ __half g_qk16[(long)MROWS * QKLD];
__device__ __half g_vt16[MROWS * HID];
__device__ __half g_att16[MROWS * HID];

__device__ __forceinline__ void cp_async16(void* smem_dst, const void* gmem_src) {
    unsigned s = (unsigned)__cvta_generic_to_shared(smem_dst);
    asm volatile("cp.async.cg.shared.global [%0], [%1], 16;\n" :: "r"(s), "l"(gmem_src));
}
__device__ __forceinline__ void cp_commit() {
    asm volatile("cp.async.commit_group;\n");
}
template <int N> __device__ __forceinline__ void cp_wait() {
    asm volatile("cp.async.wait_group %0;\n" :: "n"(N));
}
__device__ __forceinline__ unsigned packh2(float a, float b) {
    __half2 h = __floats2half2_rn(a, b);
    return *(unsigned*)&h;
}

// ---------------- generic fp16 GEMM (R5-verified) ---------------------------
// C[M,N] = alpha * A @ B^T ; A:[M,K] k-contig fp16, B:[N,K] k-contig fp16.
template <typename OutT>
__global__ __launch_bounds__(256, 2)
void gemm_f16(const __half* __restrict__ A, const __half* __restrict__ B,
              OutT* __restrict__ C,
              int K, int lda, int ldb, int ldc, float alpha)
{
    extern __shared__ unsigned smem[];
    unsigned* AsBase = smem;
    unsigned* BsBase = smem + NSTAGES * STAGE_U32;

    const int tid  = threadIdx.x;
    const int lane = tid & 31;
    const int wid  = tid >> 5;
    const int grp  = lane >> 2;
    const int tig  = lane & 3;
    const int wm = wid & 1;
    const int wn = wid >> 1;

    const int bm = blockIdx.y * BM;
    const int bn = blockIdx.x * BN;

    float acc[4][4][4];
#pragma unroll
    for (int i = 0; i < 4; i++)
#pragma unroll
        for (int j = 0; j < 4; j++)
#pragma unroll
            for (int t = 0; t < 4; t++) acc[i][j][t] = 0.0f;

    const int ntiles = K / 32;

#define ISSUE_TILE(KT, STAGE)                                                   \
    do {                                                                        \
        unsigned* as = AsBase + (STAGE) * STAGE_U32;                            \
        unsigned* bs = BsBase + (STAGE) * STAGE_U32;                            \
        _Pragma("unroll")                                                       \
        for (int i = 0; i < 2; i++) {                                           \
            int linear = tid + i * 256;                                         \
            int r  = linear >> 2;                                               \
            int c4 = (linear & 3) << 2;                                         \
            cp_async16(&as[r * ROW_U32 + c4],                                   \
                       &A[(long)(bm + r) * lda + (KT) * 32 + c4 * 2]);          \
            cp_async16(&bs[r * ROW_U32 + c4],                                   \
                       &B[(long)(bn + r) * ldb + (KT) * 32 + c4 * 2]);          \
        }                                                                       \
        cp_commit();                                                            \
    } while (0)

    ISSUE_TILE(0, 0);
    if (ntiles > 1) ISSUE_TILE(1, 1);
    else cp_commit();

    for (int kt = 0; kt < ntiles; kt++) {
        const int cur = kt % NSTAGES;
        if (kt + 2 < ntiles) {
            ISSUE_TILE(kt + 2, (kt + 2) % NSTAGES);
            cp_wait<2>();
        } else if (kt + 1 < ntiles) {
            cp_wait<1>();
        } else {
            cp_wait<0>();
        }
        __syncthreads();

        const unsigned* as = AsBase + cur * STAGE_U32;
        const unsigned* bs = BsBase + cur * STAGE_U32;

#pragma unroll
        for (int s = 0; s < 2; s++) {
            unsigned af[4][4], bf[4][2];
            const int p0 = s * 8 + tig;
#pragma unroll
            for (int mt = 0; mt < 4; mt++) {
                int m = wm * 64 + mt * 16 + grp;
                af[mt][0] = as[m * ROW_U32 + p0];
                af[mt][1] = as[(m + 8) * ROW_U32 + p0];
                af[mt][2] = as[m * ROW_U32 + p0 + 4];
                af[mt][3] = as[(m + 8) * ROW_U32 + p0 + 4];
            }
#pragma unroll
            for (int nt = 0; nt < 4; nt++) {
                int n = wn * 32 + nt * 8 + grp;
                bf[nt][0] = bs[n * ROW_U32 + p0];
                bf[nt][1] = bs[n * ROW_U32 + p0 + 4];
            }
#pragma unroll
            for (int mt = 0; mt < 4; mt++)
#pragma unroll
                for (int nt = 0; nt < 4; nt++) {
                    asm volatile(
                        "mma.sync.aligned.m16n8k16.row.col.f32.f16.f16.f32 "
                        "{%0,%1,%2,%3}, {%4,%5,%6,%7}, {%8,%9}, {%0,%1,%2,%3};"
                        : "+f"(acc[mt][nt][0]), "+f"(acc[mt][nt][1]),
                          "+f"(acc[mt][nt][2]), "+f"(acc[mt][nt][3])
                        : "r"(af[mt][0]), "r"(af[mt][1]),
                          "r"(af[mt][2]), "r"(af[mt][3]),
                          "r"(bf[nt][0]), "r"(bf[nt][1]));
                }
        }
        __syncthreads();
    }
#undef ISSUE_TILE

#pragma unroll
    for (int mt = 0; mt < 4; mt++) {
        int r0 = bm + wm * 64 + mt * 16 + grp;
        int r1 = r0 + 8;
#pragma unroll
        for (int nt = 0; nt < 4; nt++) {
            int c = bn + wn * 32 + nt * 8 + tig * 2;
            float x0 = acc[mt][nt][0] * alpha, x1 = acc[mt][nt][1] * alpha;
            float x2 = acc[mt][nt][2] * alpha, x3 = acc[mt][nt][3] * alpha;
            if (sizeof(OutT) == 2) {
                *(unsigned*)&((__half*)C)[(long)r0 * ldc + c] = packh2(x0, x1);
                *(unsigned*)&((__half*)C)[(long)r1 * ldc + c] = packh2(x2, x3);
            } else {
                *(float2*)&((float*)C)[(long)r0 * ldc + c] = make_float2(x0, x1);
                *(float2*)&((float*)C)[(long)r1 * ldc + c] = make_float2(x2, x3);
            }
        }
    }
}

// ---------------- fused flash attention, 64q x 64k, 128 thr, 2 CTA/SM -------
// QK: [token][4096] fp16 (Q cols h*128, K cols 2048+h*128). Vt: [dim][token].
// Grid: (32 q-tiles, 32 z). Block 128 (4 warps x 16 q-rows).
__global__ __launch_bounds__(128, 2)
void flash_kernel(const __half* __restrict__ QK, const __half* __restrict__ Vt,
                  const float* __restrict__ mask, __half* __restrict__ O)
{
    extern __shared__ unsigned sm[];
    unsigned* Qs = sm;                       // 64 x KROW
    unsigned* Ks = sm + QS_U32;              // 2 stages of 64 x KROW
    unsigned* Vs = sm + QS_U32 + 2 * KS_U32; // 2 stages of 128 x VROWU

    const int tid  = threadIdx.x;
    const int lane = tid & 31;
    const int wq   = tid >> 5;          // 0..3, 16-row band
    const int grp  = lane >> 2;
    const int tig  = lane & 3;

    const int z  = blockIdx.y;
    const int b  = z >> 4;
    const int h  = z & 15;
    const int qt = blockIdx.x;

    const __half* Qg = QK + (long)(b * 2048 + qt * 64) * QKLD + h * 128;
    const __half* Kg = QK + (long)(b * 2048) * QKLD + 2048 + h * 128;
    const __half* Vg = Vt + (long)(h * 128) * (long)MROWS + b * 2048;
    const float*  Mg = mask + (long)(qt * 64) * 2048;

#define ISSUE_KV(KT, STAGE)                                                     \
    do {                                                                        \
        unsigned* ks = Ks + (STAGE) * KS_U32;                                   \
        unsigned* vs = Vs + (STAGE) * VS_U32;                                   \
        _Pragma("unroll")                                                       \
        for (int i = 0; i < 8; i++) {                                           \
            int lin = tid + i * 128;                                            \
            int kr  = lin >> 4;                  /* 0..63 key row */            \
            int kc  = (lin & 15) << 2;           /* u32 col 0..60 */            \
            cp_async16(&ks[kr * KROW + kc],                                     \
                       Kg + (long)((KT) * 64 + kr) * QKLD + kc * 2);            \
            int vr  = lin >> 3;                  /* 0..127 dim row */           \
            int vc  = (lin & 7) << 2;            /* u32 col 0..28 */            \
            cp_async16(&vs[vr * VROWU + vc],                                    \
                       Vg + (long)vr * MROWS + (KT) * 64 + vc * 2);             \
        }                                                                       \
        cp_commit();                                                            \
    } while (0)

    // Q (group 0, together with KV tile 0)
#pragma unroll
    for (int i = 0; i < 8; i++) {
        int lin = tid + i * 128;
        int r  = lin >> 4;
        int c4 = (lin & 15) << 2;
        cp_async16(&Qs[r * KROW + c4], Qg + (long)r * QKLD + c4 * 2);
    }
    ISSUE_KV(0, 0);
    ISSUE_KV(1, 1);

    float acc_o[16][4];
#pragma unroll
    for (int i = 0; i < 16; i++)
#pragma unroll
        for (int t = 0; t < 4; t++) acc_o[i][t] = 0.0f;
    float m0 = -1e30f, m1 = -1e30f, l0 = 0.0f, l1 = 0.0f;
    unsigned qf[8][4];

    const float alpha = 0.08838834764831845f;

    for (int kt = 0; kt < 32; kt++) {
        const int cur = kt & 1;
        if (kt + 1 < 32) cp_wait<1>(); else cp_wait<0>();
        __syncthreads();

        if (kt == 0) {
#pragma unroll
            for (int ks = 0; ks < 8; ks++) {
                int m = wq * 16 + grp;
                qf[ks][0] = Qs[m * KROW + ks * 8 + tig];
                qf[ks][1] = Qs[(m + 8) * KROW + ks * 8 + tig];
                qf[ks][2] = Qs[m * KROW + ks * 8 + tig + 4];
                qf[ks][3] = Qs[(m + 8) * KROW + ks * 8 + tig + 4];
            }
        }

        // ---- S = Q K^T  (64 keys -> 8 n-tiles) ----
        float s[8][4];
#pragma unroll
        for (int nt = 0; nt < 8; nt++)
#pragma unroll
            for (int t = 0; t < 4; t++) s[nt][t] = 0.0f;

        const unsigned* ksm = Ks + cur * KS_U32;
#pragma unroll
        for (int nt = 0; nt < 8; nt++) {
#pragma unroll
            for (int ks = 0; ks < 8; ks++) {
                unsigned b0 = ksm[(nt * 8 + grp) * KROW + ks * 8 + tig];
                unsigned b1 = ksm[(nt * 8 + grp) * KROW + ks * 8 + tig + 4];
                asm volatile(
                    "mma.sync.aligned.m16n8k16.row.col.f32.f16.f16.f32 "
                    "{%0,%1,%2,%3}, {%4,%5,%6,%7}, {%8,%9}, {%0,%1,%2,%3};"
                    : "+f"(s[nt][0]), "+f"(s[nt][1]), "+f"(s[nt][2]), "+f"(s[nt][3])
                    : "r"(qf[ks][0]), "r"(qf[ks][1]), "r"(qf[ks][2]), "r"(qf[ks][3]),
                      "r"(b0), "r"(b1));
            }
        }

        // ---- scale + mask + online softmax ----
        const int qr0 = wq * 16 + grp;
        float mn0 = m0, mn1 = m1;
#pragma unroll
        for (int nt = 0; nt < 8; nt++) {
            int kc = kt * 64 + nt * 8 + tig * 2;
            float2 mk0 = *(const float2*)&Mg[(long)qr0 * 2048 + kc];
            float2 mk1 = *(const float2*)&Mg[(long)(qr0 + 8) * 2048 + kc];
            s[nt][0] = s[nt][0] * alpha + mk0.x;
            s[nt][1] = s[nt][1] * alpha + mk0.y;
            s[nt][2] = s[nt][2] * alpha + mk1.x;
            s[nt][3] = s[nt][3] * alpha + mk1.y;
            mn0 = fmaxf(mn0, fmaxf(s[nt][0], s[nt][1]));
            mn1 = fmaxf(mn1, fmaxf(s[nt][2], s[nt][3]));
        }
        mn0 = fmaxf(mn0, __shfl_xor_sync(0xffffffffu, mn0, 1));
        mn0 = fmaxf(mn0, __shfl_xor_sync(0xffffffffu, mn0, 2));
        mn1 = fmaxf(mn1, __shfl_xor_sync(0xffffffffu, mn1, 1));
        mn1 = fmaxf(mn1, __shfl_xor_sync(0xffffffffu, mn1, 2));

        float c0 = __expf(m0 - mn0);
        float c1 = __expf(m1 - mn1);
        m0 = mn0; m1 = mn1;

        unsigned pf[8][2];
        float ls0 = 0.0f, ls1 = 0.0f;
#pragma unroll
        for (int nt = 0; nt < 8; nt++) {
            float e0 = __expf(s[nt][0] - mn0);
            float e1 = __expf(s[nt][1] - mn0);
            float e2 = __expf(s[nt][2] - mn1);
            float e3 = __expf(s[nt][3] - mn1);
            ls0 += e0 + e1; ls1 += e2 + e3;
            pf[nt][0] = packh2(e0, e1);
            pf[nt][1] = packh2(e2, e3);
        }
        ls0 += __shfl_xor_sync(0xffffffffu, ls0, 1);
        ls0 += __shfl_xor_sync(0xffffffffu, ls0, 2);
        ls1 += __shfl_xor_sync(0xffffffffu, ls1, 1);
        ls1 += __shfl_xor_sync(0xffffffffu, ls1, 2);
        l0 = c0 * l0 + ls0;
        l1 = c1 * l1 + ls1;

#pragma unroll
        for (int dn = 0; dn < 16; dn++) {
            acc_o[dn][0] *= c0; acc_o[dn][1] *= c0;
            acc_o[dn][2] *= c1; acc_o[dn][3] *= c1;
        }

        // ---- O += P V  (64-key k-dim -> 4 k16 steps) ----
        const unsigned* vsm = Vs + cur * VS_U32;
#pragma unroll
        for (int dn = 0; dn < 16; dn++) {
#pragma unroll
            for (int kp = 0; kp < 4; kp++) {
                unsigned vb0 = vsm[(dn * 8 + grp) * VROWU + kp * 8 + tig];
                unsigned vb1 = vsm[(dn * 8 + grp) * VROWU + kp * 8 + tig + 4];
                asm volatile(
                    "mma.sync.aligned.m16n8k16.row.col.f32.f16.f16.f32 "
                    "{%0,%1,%2,%3}, {%4,%5,%6,%7}, {%8,%9}, {%0,%1,%2,%3};"
                    : "+f"(acc_o[dn][0]), "+f"(acc_o[dn][1]),
                      "+f"(acc_o[dn][2]), "+f"(acc_o[dn][3])
                    : "r"(pf[2 * kp][0]), "r"(pf[2 * kp][1]),
                      "r"(pf[2 * kp + 1][0]), "r"(pf[2 * kp + 1][1]),
                      "r"(vb0), "r"(vb1));
            }
        }

        __syncthreads();
        if (kt + 2 < 32) ISSUE_KV(kt + 2, cur);
    }
#undef ISSUE_KV

    // ---- epilogue ----
    float inv0 = 1.0f / l0;
    float inv1 = 1.0f / l1;
    long t0 = (long)(b * 2048 + qt * 64 + wq * 16 + grp);
    long t1 = t0 + 8;
#pragma unroll
    for (int dn = 0; dn < 16; dn++) {
        int col = h * 128 + dn * 8 + tig * 2;
        *(unsigned*)&O[t0 * HID + col] = packh2(acc_o[dn][0] * inv0, acc_o[dn][1] * inv0);
        *(unsigned*)&O[t1 * HID + col] = packh2(acc_o[dn][2] * inv1, acc_o[dn][3] * inv1);
    }
}

// fp32 -> fp16 elementwise (n multiple of 4)
__global__ void f2h_kernel(const float* __restrict__ in, __half* __restrict__ out, long n)
{
    long i = ((long)blockIdx.x * blockDim.x + threadIdx.x) * 4;
    if (i < n) {
        float4 v = *(const float4*)&in[i];
        *(__half2*)&out[i]     = __floats2half2_rn(v.x, v.y);
        *(__half2*)&out[i + 2] = __floats2half2_rn(v.z, v.w);
    }
}

extern "C" void kernel_launch(void* const* d_in, const int* in_sizes, int n_in,
                              void* d_out, int out_size)
{
    (void)in_sizes; (void)n_in; (void)out_size;
    const float* hidden = (const float*)d_in[0];
    const float* mask   = (const float*)d_in[1];
    const float* Wq     = (const float*)d_in[2];
    const float* Wk     = (const float*)d_in[3];
    const float* Wv     = (const float*)d_in[4];
    const float* Wo     = (const float*)d_in[5];
    float* out = (float*)d_out;

    __half *h16, *wqk16, *wv16, *wo16, *qk16, *vt16, *att16;
    cudaGetSymbolAddress((void**)&h16,   g_h16);
    cudaGetSymbolAddress((void**)&wqk16, g_wqk16);
    cudaGetSymbolAddress((void**)&wv16,  g_wv16);
    cudaGetSymbolAddress((void**)&wo16,  g_wo16);
    cudaGetSymbolAddress((void**)&qk16,  g_qk16);
    cudaGetSymbolAddress((void**)&vt16,  g_vt16);
    cudaGetSymbolAddress((void**)&att16, g_att16);

    cudaFuncSetAttribute(gemm_f16<__half>,
                         cudaFuncAttributeMaxDynamicSharedMemorySize, SMEM_BYTES16);
    cudaFuncSetAttribute(gemm_f16<float>,
                         cudaFuncAttributeMaxDynamicSharedMemorySize, SMEM_BYTES16);
    cudaFuncSetAttribute(flash_kernel,
                         cudaFuncAttributeMaxDynamicSharedMemorySize, FLASH_SMEM);

    // 0: convert to fp16 (Wq|Wk concatenated)
    f2h_kernel<<<(MROWS * HID) / 1024, 256>>>(hidden, h16, (long)MROWS * HID);
    f2h_kernel<<<(HID * HID) / 1024, 256>>>(Wq, wqk16, (long)HID * HID);
    f2h_kernel<<<(HID * HID) / 1024, 256>>>(Wk, wqk16 + (long)HID * HID, (long)HID * HID);
    f2h_kernel<<<(HID * HID) / 1024, 256>>>(Wv, wv16, (long)HID * HID);
    f2h_kernel<<<(HID * HID) / 1024, 256>>>(Wo, wo16, (long)HID * HID);

    dim3 thr(256);

    // 1: qk16 = h16 @ [Wq|Wk]^T   (M=4096, N=4096, K=2048)
    dim3 gQK(QKLD / BN, MROWS / BM, 1);
    gemm_f16<__half><<<gQK, thr, SMEM_BYTES16>>>(h16, wqk16, qk16,
                                                 HID, HID, HID, QKLD, 1.0f);

    // 2: vt16 = Wv16 @ h16^T  (M=2048, N=4096) -> [dim][token]
    dim3 gVt(MROWS / BN, HID / BM, 1);
    gemm_f16<__half><<<gVt, thr, SMEM_BYTES16>>>(wv16, h16, vt16,
                                                 HID, HID, HID, MROWS, 1.0f);

    // 3: fused attention (64-row q tiles)
    dim3 gFlash(32, 32, 1);
    flash_kernel<<<gFlash, dim3(128), FLASH_SMEM>>>(qk16, vt16, mask, att16);

    // 4: out = att16 @ Wo^T
    dim3 gOut(HID / BN, MROWS / BM, 1);
    gemm_f16<float><<<gOut, thr, SMEM_BYTES16>>>(att16, wo16, out,
                                                 HID, HID, HID, HID, 1.0f);
}

// round 8
// speedup vs baseline: 5.9106x; 1.1224x over previous
#include <cuda_runtime.h>
#include <cuda_fp16.h>
#include <math.h>

// ---------------------------------------------------------------------------
// TensorParallelAttention — fp16 mma.sync + ldmatrix fragment loads +
// f16x2 ex2 softmax. Flash at 2 CTAs/SM.
//   0. convert hidden -> h16; Wq|Wk -> wqk16; Wv -> wv16; Wo -> wo16
//   1. qk16 = h16 @ [Wq|Wk]^T     (N=4096)
//   2. vt16 = Wv16 @ h16^T        ([dim][token])
//   3. flash: att16 = softmax(aQK^T+M)V
//   4. out  = att16 @ Wo^T
// ---------------------------------------------------------------------------

#define BM 128
#define BN 128
#define ROW_U32 20
#define STAGE_U32 (128 * ROW_U32)
#define NSTAGES 3
#define SMEM_BYTES16 (NSTAGES * 2 * STAGE_U32 * 4)

#define HID 2048
#define MROWS 4096
#define QKLD 4096

#define KROW 68
#define VROWU 36
#define QS_U32 (64 * KROW)
#define KS_U32 (64 * KROW)
#define VS_U32 (128 * VROWU)
#define FLASH_SMEM ((QS_U32 + 2 * KS_U32 + 2 * VS_U32) * 4)   // 89088

__device__ __half g_h16[MROWS * HID];
__device__ __half g_wqk16[2L * HID * HID];
__device__ __half g_wv16[HID * HID];
__device__ __half g_wo16[HID * HID];
__device__ __half g_qk16[(long)MROWS * QKLD];
__device__ __half g_vt16[MROWS * HID];
__device__ __half g_att16[MROWS * HID];

__device__ __forceinline__ void cp_async16(void* smem_dst, const void* gmem_src) {
    unsigned s = (unsigned)__cvta_generic_to_shared(smem_dst);
    asm volatile("cp.async.cg.shared.global [%0], [%1], 16;\n" :: "r"(s), "l"(gmem_src));
}
__device__ __forceinline__ void cp_commit() {
    asm volatile("cp.async.commit_group;\n");
}
template <int N> __device__ __forceinline__ void cp_wait() {
    asm volatile("cp.async.wait_group %0;\n" :: "n"(N));
}
__device__ __forceinline__ unsigned packh2(float a, float b) {
    __half2 h = __floats2half2_rn(a, b);
    return *(unsigned*)&h;
}
__device__ __forceinline__ void ldsm4(unsigned& r0, unsigned& r1,
                                      unsigned& r2, unsigned& r3, unsigned addr) {
    asm volatile("ldmatrix.sync.aligned.m8n8.x4.shared.b16 {%0,%1,%2,%3}, [%4];"
                 : "=r"(r0), "=r"(r1), "=r"(r2), "=r"(r3) : "r"(addr));
}
#define MMA16816(D, A0, A1, A2, A3, B0, B1)                                     \
    asm volatile(                                                               \
        "mma.sync.aligned.m16n8k16.row.col.f32.f16.f16.f32 "                    \
        "{%0,%1,%2,%3}, {%4,%5,%6,%7}, {%8,%9}, {%0,%1,%2,%3};"                 \
        : "+f"((D)[0]), "+f"((D)[1]), "+f"((D)[2]), "+f"((D)[3])                \
        : "r"(A0), "r"(A1), "r"(A2), "r"(A3), "r"(B0), "r"(B1))

// ---------------- generic fp16 GEMM, ldmatrix fragments ---------------------
// C[M,N] = alpha * A @ B^T ; A:[M,K] k-contig fp16, B:[N,K] k-contig fp16.
template <typename OutT>
__global__ __launch_bounds__(256, 2)
void gemm_f16(const __half* __restrict__ A, const __half* __restrict__ B,
              OutT* __restrict__ C,
              int K, int lda, int ldb, int ldc, float alpha)
{
    extern __shared__ unsigned smem[];
    const unsigned smb = (unsigned)__cvta_generic_to_shared(smem);

    const int tid  = threadIdx.x;
    const int lane = tid & 31;
    const int wid  = tid >> 5;
    const int grp  = lane >> 2;
    const int tig  = lane & 3;
    const int wm = wid & 1;
    const int wn = wid >> 1;

    // ldmatrix lane address components
    const int a_row = ((lane >> 3) & 1) * 8 + (lane & 7);   // A: rows 0-15
    const int a_col = (lane >> 4) * 4;                      // A: k0/k8 (u32)
    const int b_row = ((lane >> 4) << 3) + (lane & 7);      // B: rows 0-15
    const int b_col = ((lane >> 3) & 1) << 2;               // B: k0/k8 (u32)

    const int bm = blockIdx.y * BM;
    const int bn = blockIdx.x * BN;

    float acc[4][4][4];
#pragma unroll
    for (int i = 0; i < 4; i++)
#pragma unroll
        for (int j = 0; j < 4; j++)
#pragma unroll
            for (int t = 0; t < 4; t++) acc[i][j][t] = 0.0f;

    const int ntiles = K / 32;

#define ISSUE_TILE(KT, STAGE)                                                   \
    do {                                                                        \
        unsigned* as = smem + (STAGE) * STAGE_U32;                              \
        unsigned* bs = smem + (NSTAGES + (STAGE)) * STAGE_U32;                  \
        _Pragma("unroll")                                                       \
        for (int i = 0; i < 2; i++) {                                           \
            int linear = tid + i * 256;                                         \
            int r  = linear >> 2;                                               \
            int c4 = (linear & 3) << 2;                                         \
            cp_async16(&as[r * ROW_U32 + c4],                                   \
                       &A[(long)(bm + r) * lda + (KT) * 32 + c4 * 2]);          \
            cp_async16(&bs[r * ROW_U32 + c4],                                   \
                       &B[(long)(bn + r) * ldb + (KT) * 32 + c4 * 2]);          \
        }                                                                       \
        cp_commit();                                                            \
    } while (0)

    ISSUE_TILE(0, 0);
    if (ntiles > 1) ISSUE_TILE(1, 1);
    else cp_commit();

    for (int kt = 0; kt < ntiles; kt++) {
        const int cur = kt % NSTAGES;
        if (kt + 2 < ntiles) {
            ISSUE_TILE(kt + 2, (kt + 2) % NSTAGES);
            cp_wait<2>();
        } else if (kt + 1 < ntiles) {
            cp_wait<1>();
        } else {
            cp_wait<0>();
        }
        __syncthreads();

        const unsigned abase = smb + (cur * STAGE_U32) * 4;
        const unsigned bbase = smb + ((NSTAGES + cur) * STAGE_U32) * 4;

#pragma unroll
        for (int s = 0; s < 2; s++) {
            const int p0 = s * 8;
            unsigned af[4][4], bf[4][2];
#pragma unroll
            for (int mt = 0; mt < 4; mt++)
                ldsm4(af[mt][0], af[mt][1], af[mt][2], af[mt][3],
                      abase + 4 * ((wm * 64 + mt * 16 + a_row) * ROW_U32 + p0 + a_col));
#pragma unroll
            for (int np = 0; np < 2; np++)
                ldsm4(bf[2 * np][0], bf[2 * np][1], bf[2 * np + 1][0], bf[2 * np + 1][1],
                      bbase + 4 * ((wn * 32 + np * 16 + b_row) * ROW_U32 + p0 + b_col));
#pragma unroll
            for (int mt = 0; mt < 4; mt++)
#pragma unroll
                for (int nt = 0; nt < 4; nt++)
                    MMA16816(acc[mt][nt], af[mt][0], af[mt][1], af[mt][2], af[mt][3],
                             bf[nt][0], bf[nt][1]);
        }
        __syncthreads();
    }
#undef ISSUE_TILE

#pragma unroll
    for (int mt = 0; mt < 4; mt++) {
        int r0 = bm + wm * 64 + mt * 16 + grp;
        int r1 = r0 + 8;
#pragma unroll
        for (int nt = 0; nt < 4; nt++) {
            int c = bn + wn * 32 + nt * 8 + tig * 2;
            float x0 = acc[mt][nt][0] * alpha, x1 = acc[mt][nt][1] * alpha;
            float x2 = acc[mt][nt][2] * alpha, x3 = acc[mt][nt][3] * alpha;
            if (sizeof(OutT) == 2) {
                *(unsigned*)&((__half*)C)[(long)r0 * ldc + c] = packh2(x0, x1);
                *(unsigned*)&((__half*)C)[(long)r1 * ldc + c] = packh2(x2, x3);
            } else {
                *(float2*)&((float*)C)[(long)r0 * ldc + c] = make_float2(x0, x1);
                *(float2*)&((float*)C)[(long)r1 * ldc + c] = make_float2(x2, x3);
            }
        }
    }
}

// ---------------- fused flash attention, 64q x 64k, 128 thr, 2 CTA/SM -------
__global__ __launch_bounds__(128, 2)
void flash_kernel(const __half* __restrict__ QK, const __half* __restrict__ Vt,
                  const float* __restrict__ mask, __half* __restrict__ O)
{
    extern __shared__ unsigned sm[];
    unsigned* Qs = sm;
    const unsigned smb = (unsigned)__cvta_generic_to_shared(sm);
    const unsigned ksb = smb + QS_U32 * 4;
    const unsigned vsb = smb + (QS_U32 + 2 * KS_U32) * 4;
    unsigned* Ks = sm + QS_U32;
    unsigned* Vs = sm + QS_U32 + 2 * KS_U32;

    const int tid  = threadIdx.x;
    const int lane = tid & 31;
    const int wq   = tid >> 5;
    const int grp  = lane >> 2;
    const int tig  = lane & 3;
    const int b_row = ((lane >> 4) << 3) + (lane & 7);
    const int b_col = ((lane >> 3) & 1) << 2;

    const int z  = blockIdx.y;
    const int b  = z >> 4;
    const int h  = z & 15;
    const int qt = blockIdx.x;

    const __half* Qg = QK + (long)(b * 2048 + qt * 64) * QKLD + h * 128;
    const __half* Kg = QK + (long)(b * 2048) * QKLD + 2048 + h * 128;
    const __half* Vg = Vt + (long)(h * 128) * (long)MROWS + b * 2048;
    const float*  Mg = mask + (long)(qt * 64) * 2048;

#define ISSUE_KV(KT, STAGE)                                                     \
    do {                                                                        \
        unsigned* ks = Ks + (STAGE) * KS_U32;                                   \
        unsigned* vs = Vs + (STAGE) * VS_U32;                                   \
        _Pragma("unroll")                                                       \
        for (int i = 0; i < 8; i++) {                                           \
            int lin = tid + i * 128;                                            \
            int kr  = lin >> 4;                                                 \
            int kc  = (lin & 15) << 2;                                          \
            cp_async16(&ks[kr * KROW + kc],                                     \
                       Kg + (long)((KT) * 64 + kr) * QKLD + kc * 2);            \
            int vr  = lin >> 3;                                                 \
            int vc  = (lin & 7) << 2;                                           \
            cp_async16(&vs[vr * VROWU + vc],                                    \
                       Vg + (long)vr * MROWS + (KT) * 64 + vc * 2);             \
        }                                                                       \
        cp_commit();                                                            \
    } while (0)

#pragma unroll
    for (int i = 0; i < 8; i++) {
        int lin = tid + i * 128;
        int r  = lin >> 4;
        int c4 = (lin & 15) << 2;
        cp_async16(&Qs[r * KROW + c4], Qg + (long)r * QKLD + c4 * 2);
    }
    ISSUE_KV(0, 0);
    ISSUE_KV(1, 1);

    float acc_o[16][4];
#pragma unroll
    for (int i = 0; i < 16; i++)
#pragma unroll
        for (int t = 0; t < 4; t++) acc_o[i][t] = 0.0f;
    float m0 = -1e30f, m1 = -1e30f, l0 = 0.0f, l1 = 0.0f;
    unsigned qf[8][4];

    const float alpha = 0.08838834764831845f;
    const float LOG2E = 1.44269504f;

    for (int kt = 0; kt < 32; kt++) {
        const int cur = kt & 1;
        if (kt + 1 < 32) cp_wait<1>(); else cp_wait<0>();
        __syncthreads();

        if (kt == 0) {
#pragma unroll
            for (int ks = 0; ks < 8; ks++) {
                int m = wq * 16 + grp;
                qf[ks][0] = Qs[m * KROW + ks * 8 + tig];
                qf[ks][1] = Qs[(m + 8) * KROW + ks * 8 + tig];
                qf[ks][2] = Qs[m * KROW + ks * 8 + tig + 4];
                qf[ks][3] = Qs[(m + 8) * KROW + ks * 8 + tig + 4];
            }
        }

        // ---- S = Q K^T (ldmatrix fragments) ----
        float s[8][4];
#pragma unroll
        for (int nt = 0; nt < 8; nt++)
#pragma unroll
            for (int t = 0; t < 4; t++) s[nt][t] = 0.0f;

        const unsigned kb = ksb + cur * KS_U32 * 4;
#pragma unroll
        for (int np = 0; np < 4; np++) {
#pragma unroll
            for (int ks = 0; ks < 8; ks++) {
                unsigned f0, f1, f2, f3;
                ldsm4(f0, f1, f2, f3,
                      kb + 4 * ((np * 16 + b_row) * KROW + ks * 8 + b_col));
                MMA16816(s[2 * np],     qf[ks][0], qf[ks][1], qf[ks][2], qf[ks][3], f0, f1);
                MMA16816(s[2 * np + 1], qf[ks][0], qf[ks][1], qf[ks][2], qf[ks][3], f2, f3);
            }
        }

        // ---- scale + mask + online softmax (f16x2 ex2) ----
        const int qr0 = wq * 16 + grp;
        float mn0 = m0, mn1 = m1;
#pragma unroll
        for (int nt = 0; nt < 8; nt++) {
            int kc = kt * 64 + nt * 8 + tig * 2;
            float2 mk0 = *(const float2*)&Mg[(long)qr0 * 2048 + kc];
            float2 mk1 = *(const float2*)&Mg[(long)(qr0 + 8) * 2048 + kc];
            s[nt][0] = s[nt][0] * alpha + mk0.x;
            s[nt][1] = s[nt][1] * alpha + mk0.y;
            s[nt][2] = s[nt][2] * alpha + mk1.x;
            s[nt][3] = s[nt][3] * alpha + mk1.y;
            mn0 = fmaxf(mn0, fmaxf(s[nt][0], s[nt][1]));
            mn1 = fmaxf(mn1, fmaxf(s[nt][2], s[nt][3]));
        }
        mn0 = fmaxf(mn0, __shfl_xor_sync(0xffffffffu, mn0, 1));
        mn0 = fmaxf(mn0, __shfl_xor_sync(0xffffffffu, mn0, 2));
        mn1 = fmaxf(mn1, __shfl_xor_sync(0xffffffffu, mn1, 1));
        mn1 = fmaxf(mn1, __shfl_xor_sync(0xffffffffu, mn1, 2));

        float c0 = __expf(m0 - mn0);
        float c1 = __expf(m1 - mn1);
        m0 = mn0; m1 = mn1;
        const float mn0L = mn0 * LOG2E;
        const float mn1L = mn1 * LOG2E;

        unsigned pf[8][2];
        float ls0 = 0.0f, ls1 = 0.0f;
#pragma unroll
        for (int nt = 0; nt < 8; nt++) {
            float t0 = fmaf(s[nt][0], LOG2E, -mn0L);
            float t1 = fmaf(s[nt][1], LOG2E, -mn0L);
            float t2 = fmaf(s[nt][2], LOG2E, -mn1L);
            float t3 = fmaf(s[nt][3], LOG2E, -mn1L);
            unsigned x0 = packh2(t0, t1);
            unsigned x1 = packh2(t2, t3);
            asm("ex2.approx.f16x2 %0, %1;" : "=r"(pf[nt][0]) : "r"(x0));
            asm("ex2.approx.f16x2 %0, %1;" : "=r"(pf[nt][1]) : "r"(x1));
            float2 f0 = __half22float2(*(__half2*)&pf[nt][0]);
            float2 f1 = __half22float2(*(__half2*)&pf[nt][1]);
            ls0 += f0.x + f0.y;
            ls1 += f1.x + f1.y;
        }
        ls0 += __shfl_xor_sync(0xffffffffu, ls0, 1);
        ls0 += __shfl_xor_sync(0xffffffffu, ls0, 2);
        ls1 += __shfl_xor_sync(0xffffffffu, ls1, 1);
        ls1 += __shfl_xor_sync(0xffffffffu, ls1, 2);
        l0 = c0 * l0 + ls0;
        l1 = c1 * l1 + ls1;

#pragma unroll
        for (int dn = 0; dn < 16; dn++) {
            acc_o[dn][0] *= c0; acc_o[dn][1] *= c0;
            acc_o[dn][2] *= c1; acc_o[dn][3] *= c1;
        }

        // ---- O += P V (ldmatrix fragments) ----
        const unsigned vb = vsb + cur * VS_U32 * 4;
#pragma unroll
        for (int dp = 0; dp < 8; dp++) {
#pragma unroll
            for (int kp = 0; kp < 4; kp++) {
                unsigned f0, f1, f2, f3;
                ldsm4(f0, f1, f2, f3,
                      vb + 4 * ((dp * 16 + b_row) * VROWU + kp * 8 + b_col));
                MMA16816(acc_o[2 * dp],     pf[2 * kp][0], pf[2 * kp][1],
                         pf[2 * kp + 1][0], pf[2 * kp + 1][1], f0, f1);
                MMA16816(acc_o[2 * dp + 1], pf[2 * kp][0], pf[2 * kp][1],
                         pf[2 * kp + 1][0], pf[2 * kp + 1][1], f2, f3);
            }
        }

        __syncthreads();
        if (kt + 2 < 32) ISSUE_KV(kt + 2, cur);
    }
#undef ISSUE_KV

    float inv0 = 1.0f / l0;
    float inv1 = 1.0f / l1;
    long t0 = (long)(b * 2048 + qt * 64 + wq * 16 + grp);
    long t1 = t0 + 8;
#pragma unroll
    for (int dn = 0; dn < 16; dn++) {
        int col = h * 128 + dn * 8 + tig * 2;
        *(unsigned*)&O[t0 * HID + col] = packh2(acc_o[dn][0] * inv0, acc_o[dn][1] * inv0);
        *(unsigned*)&O[t1 * HID + col] = packh2(acc_o[dn][2] * inv1, acc_o[dn][3] * inv1);
    }
}

// fp32 -> fp16 elementwise (n multiple of 4)
__global__ void f2h_kernel(const float* __restrict__ in, __half* __restrict__ out, long n)
{
    long i = ((long)blockIdx.x * blockDim.x + threadIdx.x) * 4;
    if (i < n) {
        float4 v = *(const float4*)&in[i];
        *(__half2*)&out[i]     = __floats2half2_rn(v.x, v.y);
        *(__half2*)&out[i + 2] = __floats2half2_rn(v.z, v.w);
    }
}

extern "C" void kernel_launch(void* const* d_in, const int* in_sizes, int n_in,
                              void* d_out, int out_size)
{
    (void)in_sizes; (void)n_in; (void)out_size;
    const float* hidden = (const float*)d_in[0];
    const float* mask   = (const float*)d_in[1];
    const float* Wq     = (const float*)d_in[2];
    const float* Wk     = (const float*)d_in[3];
    const float* Wv     = (const float*)d_in[4];
    const float* Wo     = (const float*)d_in[5];
    float* out = (float*)d_out;

    __half *h16, *wqk16, *wv16, *wo16, *qk16, *vt16, *att16;
    cudaGetSymbolAddress((void**)&h16,   g_h16);
    cudaGetSymbolAddress((void**)&wqk16, g_wqk16);
    cudaGetSymbolAddress((void**)&wv16,  g_wv16);
    cudaGetSymbolAddress((void**)&wo16,  g_wo16);
    cudaGetSymbolAddress((void**)&qk16,  g_qk16);
    cudaGetSymbolAddress((void**)&vt16,  g_vt16);
    cudaGetSymbolAddress((void**)&att16, g_att16);

    cudaFuncSetAttribute(gemm_f16<__half>,
                         cudaFuncAttributeMaxDynamicSharedMemorySize, SMEM_BYTES16);
    cudaFuncSetAttribute(gemm_f16<float>,
                         cudaFuncAttributeMaxDynamicSharedMemorySize, SMEM_BYTES16);
    cudaFuncSetAttribute(flash_kernel,
                         cudaFuncAttributeMaxDynamicSharedMemorySize, FLASH_SMEM);

    // 0: convert to fp16 (Wq|Wk concatenated)
    f2h_kernel<<<(MROWS * HID) / 1024, 256>>>(hidden, h16, (long)MROWS * HID);
    f2h_kernel<<<(HID * HID) / 1024, 256>>>(Wq, wqk16, (long)HID * HID);
    f2h_kernel<<<(HID * HID) / 1024, 256>>>(Wk, wqk16 + (long)HID * HID, (long)HID * HID);
    f2h_kernel<<<(HID * HID) / 1024, 256>>>(Wv, wv16, (long)HID * HID);
    f2h_kernel<<<(HID * HID) / 1024, 256>>>(Wo, wo16, (long)HID * HID);

    dim3 thr(256);

    // 1: qk16 = h16 @ [Wq|Wk]^T
    dim3 gQK(QKLD / BN, MROWS / BM, 1);
    gemm_f16<__half><<<gQK, thr, SMEM_BYTES16>>>(h16, wqk16, qk16,
                                                 HID, HID, HID, QKLD, 1.0f);

    // 2: vt16 = Wv16 @ h16^T -> [dim][token]
    dim3 gVt(MROWS / BN, HID / BM, 1);
    gemm_f16<__half><<<gVt, thr, SMEM_BYTES16>>>(wv16, h16, vt16,
                                                 HID, HID, HID, MROWS, 1.0f);

    // 3: fused attention
    dim3 gFlash(32, 32, 1);
    flash_kernel<<<gFlash, dim3(128), FLASH_SMEM>>>(qk16, vt16, mask, att16);

    // 4: out = att16 @ Wo^T
    dim3 gOut(HID / BN, MROWS / BM, 1);
    gemm_f16<float><<<gOut, thr, SMEM_BYTES16>>>(att16, wo16, out,
                                                 HID, HID, HID, HID, 1.0f);
}

// round 9
// speedup vs baseline: 6.3834x; 1.0800x over previous
#include <cuda_runtime.h>
#include <cuda_fp16.h>
#include <math.h>

// ---------------------------------------------------------------------------
// TensorParallelAttention — fp16 mma.sync + ldmatrix + f16x2 ex2 softmax.
//   0. f2h_all: hidden,Wq|Wk,Wv,Wo,mask -> fp16 (one launch)
//   1. fused GEMM launch: qk16 = h16 @ [Wq|Wk]^T  AND  vt16 = Wv16 @ h16^T
//   2. flash: att16 = softmax(aQK^T+M)V   (mask prefetched to smem)
//   3. out  = att16 @ Wo^T
// ---------------------------------------------------------------------------

#define BM 128
#define BN 128
#define ROW_U32 20
#define STAGE_U32 (128 * ROW_U32)
#define NSTAGES 3
#define SMEM_BYTES16 (NSTAGES * 2 * STAGE_U32 * 4)

#define HID 2048
#define MROWS 4096
#define QKLD 4096

#define KROW 68
#define VROWU 36
#define MROW_U32 36                   // 32 data u32 (64 halves) + 4 pad
#define QS_U32 (64 * KROW)            // 4352
#define KS_U32 (64 * KROW)            // 4352 per stage
#define VS_U32 (128 * VROWU)          // 4608 per stage
#define MS_U32 (64 * MROW_U32)        // 2304 per stage
#define FLASH_SMEM ((QS_U32 + 2 * KS_U32 + 2 * VS_U32 + 2 * MS_U32) * 4) // 107520

__device__ __half g_h16[MROWS * HID];
__device__ __half g_wqk16[2L * HID * HID];
__device__ __half g_wv16[HID * HID];
__device__ __half g_wo16[HID * HID];
__device__ __half g_m16[2048L * 2048];
__device__ __half g_qk16[(long)MROWS * QKLD];
__device__ __half g_vt16[MROWS * HID];
__device__ __half g_att16[MROWS * HID];

__device__ __forceinline__ void cp_async16(void* smem_dst, const void* gmem_src) {
    unsigned s = (unsigned)__cvta_generic_to_shared(smem_dst);
    asm volatile("cp.async.cg.shared.global [%0], [%1], 16;\n" :: "r"(s), "l"(gmem_src));
}
__device__ __forceinline__ void cp_commit() {
    asm volatile("cp.async.commit_group;\n");
}
template <int N> __device__ __forceinline__ void cp_wait() {
    asm volatile("cp.async.wait_group %0;\n" :: "n"(N));
}
__device__ __forceinline__ unsigned packh2(float a, float b) {
    __half2 h = __floats2half2_rn(a, b);
    return *(unsigned*)&h;
}
__device__ __forceinline__ void ldsm4(unsigned& r0, unsigned& r1,
                                      unsigned& r2, unsigned& r3, unsigned addr) {
    asm volatile("ldmatrix.sync.aligned.m8n8.x4.shared.b16 {%0,%1,%2,%3}, [%4];"
                 : "=r"(r0), "=r"(r1), "=r"(r2), "=r"(r3) : "r"(addr));
}
#define MMA16816(D, A0, A1, A2, A3, B0, B1)                                     \
    asm volatile(                                                               \
        "mma.sync.aligned.m16n8k16.row.col.f32.f16.f16.f32 "                    \
        "{%0,%1,%2,%3}, {%4,%5,%6,%7}, {%8,%9}, {%0,%1,%2,%3};"                 \
        : "+f"((D)[0]), "+f"((D)[1]), "+f"((D)[2]), "+f"((D)[3])                \
        : "r"(A0), "r"(A1), "r"(A2), "r"(A3), "r"(B0), "r"(B1))

// ---------------- GEMM body (R8-verified mainloop) ---------------------------
// C[M,N] = alpha * A @ B^T ; A:[M,K] k-contig fp16, B:[N,K] k-contig fp16.
template <typename OutT>
__device__ __forceinline__
void gemm_body(const __half* __restrict__ A, const __half* __restrict__ B,
               OutT* __restrict__ C, int K, int lda, int ldb, int ldc,
               float alpha, int bm, int bn, unsigned* smem)
{
    const unsigned smb = (unsigned)__cvta_generic_to_shared(smem);

    const int tid  = threadIdx.x;
    const int lane = tid & 31;
    const int wid  = tid >> 5;
    const int grp  = lane >> 2;
    const int tig  = lane & 3;
    const int wm = wid & 1;
    const int wn = wid >> 1;

    const int a_row = ((lane >> 3) & 1) * 8 + (lane & 7);
    const int a_col = (lane >> 4) * 4;
    const int b_row = ((lane >> 4) << 3) + (lane & 7);
    const int b_col = ((lane >> 3) & 1) << 2;

    float acc[4][4][4];
#pragma unroll
    for (int i = 0; i < 4; i++)
#pragma unroll
        for (int j = 0; j < 4; j++)
#pragma unroll
            for (int t = 0; t < 4; t++) acc[i][j][t] = 0.0f;

    const int ntiles = K / 32;

#define ISSUE_TILE(KT, STAGE)                                                   \
    do {                                                                        \
        unsigned* as = smem + (STAGE) * STAGE_U32;                              \
        unsigned* bs = smem + (NSTAGES + (STAGE)) * STAGE_U32;                  \
        _Pragma("unroll")                                                       \
        for (int i = 0; i < 2; i++) {                                           \
            int linear = tid + i * 256;                                         \
            int r  = linear >> 2;                                               \
            int c4 = (linear & 3) << 2;                                         \
            cp_async16(&as[r * ROW_U32 + c4],                                   \
                       &A[(long)(bm + r) * lda + (KT) * 32 + c4 * 2]);          \
            cp_async16(&bs[r * ROW_U32 + c4],                                   \
                       &B[(long)(bn + r) * ldb + (KT) * 32 + c4 * 2]);          \
        }                                                                       \
        cp_commit();                                                            \
    } while (0)

    ISSUE_TILE(0, 0);
    if (ntiles > 1) ISSUE_TILE(1, 1);
    else cp_commit();

    for (int kt = 0; kt < ntiles; kt++) {
        const int cur = kt % NSTAGES;
        if (kt + 2 < ntiles) {
            ISSUE_TILE(kt + 2, (kt + 2) % NSTAGES);
            cp_wait<2>();
        } else if (kt + 1 < ntiles) {
            cp_wait<1>();
        } else {
            cp_wait<0>();
        }
        __syncthreads();

        const unsigned abase = smb + (cur * STAGE_U32) * 4;
        const unsigned bbase = smb + ((NSTAGES + cur) * STAGE_U32) * 4;

#pragma unroll
        for (int s = 0; s < 2; s++) {
            const int p0 = s * 8;
            unsigned af[4][4], bf[4][2];
#pragma unroll
            for (int mt = 0; mt < 4; mt++)
                ldsm4(af[mt][0], af[mt][1], af[mt][2], af[mt][3],
                      abase + 4 * ((wm * 64 + mt * 16 + a_row) * ROW_U32 + p0 + a_col));
#pragma unroll
            for (int np = 0; np < 2; np++)
                ldsm4(bf[2 * np][0], bf[2 * np][1], bf[2 * np + 1][0], bf[2 * np + 1][1],
                      bbase + 4 * ((wn * 32 + np * 16 + b_row) * ROW_U32 + p0 + b_col));
#pragma unroll
            for (int mt = 0; mt < 4; mt++)
#pragma unroll
                for (int nt = 0; nt < 4; nt++)
                    MMA16816(acc[mt][nt], af[mt][0], af[mt][1], af[mt][2], af[mt][3],
                             bf[nt][0], bf[nt][1]);
        }
        __syncthreads();
    }
#undef ISSUE_TILE

#pragma unroll
    for (int mt = 0; mt < 4; mt++) {
        int r0 = bm + wm * 64 + mt * 16 + grp;
        int r1 = r0 + 8;
#pragma unroll
        for (int nt = 0; nt < 4; nt++) {
            int c = bn + wn * 32 + nt * 8 + tig * 2;
            float x0 = acc[mt][nt][0] * alpha, x1 = acc[mt][nt][1] * alpha;
            float x2 = acc[mt][nt][2] * alpha, x3 = acc[mt][nt][3] * alpha;
            if (sizeof(OutT) == 2) {
                *(unsigned*)&((__half*)C)[(long)r0 * ldc + c] = packh2(x0, x1);
                *(unsigned*)&((__half*)C)[(long)r1 * ldc + c] = packh2(x2, x3);
            } else {
                *(float2*)&((float*)C)[(long)r0 * ldc + c] = make_float2(x0, x1);
                *(float2*)&((float*)C)[(long)r1 * ldc + c] = make_float2(x2, x3);
            }
        }
    }
}

// Fused launch: z<1024 -> qk16 = h16 @ wqk16^T ; z>=1024 -> vt16 = wv16 @ h16^T
__global__ __launch_bounds__(256, 2)
void gemm_fused(const __half* __restrict__ h16, const __half* __restrict__ wqk16,
                const __half* __restrict__ wv16, __half* __restrict__ qk16,
                __half* __restrict__ vt16)
{
    extern __shared__ unsigned smem[];
    int z = blockIdx.x;
    if (z < 1024) {
        gemm_body<__half>(h16, wqk16, qk16, HID, HID, HID, QKLD, 1.0f,
                          (z >> 5) * 128, (z & 31) * 128, smem);
    } else {
        int y = z - 1024;
        gemm_body<__half>(wv16, h16, vt16, HID, HID, HID, MROWS, 1.0f,
                          (y >> 5) * 128, (y & 31) * 128, smem);
    }
}

// Output projection: out = att16 @ Wo^T (fp32)
__global__ __launch_bounds__(256, 2)
void gemm_out(const __half* __restrict__ att16, const __half* __restrict__ wo16,
              float* __restrict__ out)
{
    extern __shared__ unsigned smem[];
    gemm_body<float>(att16, wo16, out, HID, HID, HID, HID, 1.0f,
                     blockIdx.y * BM, blockIdx.x * BN, smem);
}

// ---------------- fused flash attention, 64q x 64k, 128 thr, 2 CTA/SM -------
__global__ __launch_bounds__(128, 2)
void flash_kernel(const __half* __restrict__ QK, const __half* __restrict__ Vt,
                  const __half* __restrict__ M16, __half* __restrict__ O)
{
    extern __shared__ unsigned sm[];
    unsigned* Qs = sm;
    unsigned* Ks = sm + QS_U32;
    unsigned* Vs = sm + QS_U32 + 2 * KS_U32;
    unsigned* Ms = sm + QS_U32 + 2 * KS_U32 + 2 * VS_U32;
    const unsigned smb = (unsigned)__cvta_generic_to_shared(sm);
    const unsigned ksb = smb + QS_U32 * 4;
    const unsigned vsb = smb + (QS_U32 + 2 * KS_U32) * 4;

    const int tid  = threadIdx.x;
    const int lane = tid & 31;
    const int wq   = tid >> 5;
    const int grp  = lane >> 2;
    const int tig  = lane & 3;
    const int b_row = ((lane >> 4) << 3) + (lane & 7);
    const int b_col = ((lane >> 3) & 1) << 2;

    const int z  = blockIdx.y;
    const int b  = z >> 4;
    const int h  = z & 15;
    const int qt = blockIdx.x;

    const __half* Qg = QK + (long)(b * 2048 + qt * 64) * QKLD + h * 128;
    const __half* Kg = QK + (long)(b * 2048) * QKLD + 2048 + h * 128;
    const __half* Vg = Vt + (long)(h * 128) * (long)MROWS + b * 2048;
    const __half* Mg = M16 + (long)(qt * 64) * 2048;

#define ISSUE_KV(KT, STAGE)                                                     \
    do {                                                                        \
        unsigned* ks = Ks + (STAGE) * KS_U32;                                   \
        unsigned* vs = Vs + (STAGE) * VS_U32;                                   \
        unsigned* ms = Ms + (STAGE) * MS_U32;                                   \
        _Pragma("unroll")                                                       \
        for (int i = 0; i < 8; i++) {                                           \
            int lin = tid + i * 128;                                            \
            int kr  = lin >> 4;                                                 \
            int kc  = (lin & 15) << 2;                                          \
            cp_async16(&ks[kr * KROW + kc],                                     \
                       Kg + (long)((KT) * 64 + kr) * QKLD + kc * 2);            \
            int vr  = lin >> 3;                                                 \
            int vc  = (lin & 7) << 2;                                           \
            cp_async16(&vs[vr * VROWU + vc],                                    \
                       Vg + (long)vr * MROWS + (KT) * 64 + vc * 2);             \
        }                                                                       \
        _Pragma("unroll")                                                       \
        for (int i = 0; i < 4; i++) {                                           \
            int lin = tid + i * 128;                                            \
            int mr  = lin >> 3;                                                 \
            int mc  = (lin & 7) << 2;                                           \
            cp_async16(&ms[mr * MROW_U32 + mc],                                 \
                       Mg + (long)mr * 2048 + (KT) * 64 + mc * 2);              \
        }                                                                       \
        cp_commit();                                                            \
    } while (0)

#pragma unroll
    for (int i = 0; i < 8; i++) {
        int lin = tid + i * 128;
        int r  = lin >> 4;
        int c4 = (lin & 15) << 2;
        cp_async16(&Qs[r * KROW + c4], Qg + (long)r * QKLD + c4 * 2);
    }
    ISSUE_KV(0, 0);
    ISSUE_KV(1, 1);

    float acc_o[16][4];
#pragma unroll
    for (int i = 0; i < 16; i++)
#pragma unroll
        for (int t = 0; t < 4; t++) acc_o[i][t] = 0.0f;
    float m0 = -1e30f, m1 = -1e30f, l0 = 0.0f, l1 = 0.0f;
    unsigned qf[8][4];

    const float alpha = 0.08838834764831845f;
    const float LOG2E = 1.44269504f;

    for (int kt = 0; kt < 32; kt++) {
        const int cur = kt & 1;
        if (kt + 1 < 32) cp_wait<1>(); else cp_wait<0>();
        __syncthreads();

        if (kt == 0) {
#pragma unroll
            for (int ks = 0; ks < 8; ks++) {
                int m = wq * 16 + grp;
                qf[ks][0] = Qs[m * KROW + ks * 8 + tig];
                qf[ks][1] = Qs[(m + 8) * KROW + ks * 8 + tig];
                qf[ks][2] = Qs[m * KROW + ks * 8 + tig + 4];
                qf[ks][3] = Qs[(m + 8) * KROW + ks * 8 + tig + 4];
            }
        }

        // ---- S = Q K^T ----
        float s[8][4];
#pragma unroll
        for (int nt = 0; nt < 8; nt++)
#pragma unroll
            for (int t = 0; t < 4; t++) s[nt][t] = 0.0f;

        const unsigned kb = ksb + cur * KS_U32 * 4;
#pragma unroll
        for (int np = 0; np < 4; np++) {
#pragma unroll
            for (int ks = 0; ks < 8; ks++) {
                unsigned f0, f1, f2, f3;
                ldsm4(f0, f1, f2, f3,
                      kb + 4 * ((np * 16 + b_row) * KROW + ks * 8 + b_col));
                MMA16816(s[2 * np],     qf[ks][0], qf[ks][1], qf[ks][2], qf[ks][3], f0, f1);
                MMA16816(s[2 * np + 1], qf[ks][0], qf[ks][1], qf[ks][2], qf[ks][3], f2, f3);
            }
        }

        // ---- scale + mask (smem) + online softmax (f16x2 ex2) ----
        const int qr0 = wq * 16 + grp;
        const unsigned* msm = Ms + cur * MS_U32;
        float mn0 = m0, mn1 = m1;
#pragma unroll
        for (int nt = 0; nt < 8; nt++) {
            unsigned u0 = msm[qr0 * MROW_U32 + nt * 4 + tig];
            unsigned u1 = msm[(qr0 + 8) * MROW_U32 + nt * 4 + tig];
            float2 mk0 = __half22float2(*(__half2*)&u0);
            float2 mk1 = __half22float2(*(__half2*)&u1);
            s[nt][0] = fmaf(s[nt][0], alpha, mk0.x);
            s[nt][1] = fmaf(s[nt][1], alpha, mk0.y);
            s[nt][2] = fmaf(s[nt][2], alpha, mk1.x);
            s[nt][3] = fmaf(s[nt][3], alpha, mk1.y);
            mn0 = fmaxf(mn0, fmaxf(s[nt][0], s[nt][1]));
            mn1 = fmaxf(mn1, fmaxf(s[nt][2], s[nt][3]));
        }
        mn0 = fmaxf(mn0, __shfl_xor_sync(0xffffffffu, mn0, 1));
        mn0 = fmaxf(mn0, __shfl_xor_sync(0xffffffffu, mn0, 2));
        mn1 = fmaxf(mn1, __shfl_xor_sync(0xffffffffu, mn1, 1));
        mn1 = fmaxf(mn1, __shfl_xor_sync(0xffffffffu, mn1, 2));

        float c0 = __expf(m0 - mn0);
        float c1 = __expf(m1 - mn1);
        m0 = mn0; m1 = mn1;
        const float mn0L = mn0 * LOG2E;
        const float mn1L = mn1 * LOG2E;

        unsigned pf[8][2];
        float ls0 = 0.0f, ls1 = 0.0f;
#pragma unroll
        for (int nt = 0; nt < 8; nt++) {
            float t0 = fmaf(s[nt][0], LOG2E, -mn0L);
            float t1 = fmaf(s[nt][1], LOG2E, -mn0L);
            float t2 = fmaf(s[nt][2], LOG2E, -mn1L);
            float t3 = fmaf(s[nt][3], LOG2E, -mn1L);
            unsigned x0 = packh2(t0, t1);
            unsigned x1 = packh2(t2, t3);
            asm("ex2.approx.f16x2 %0, %1;" : "=r"(pf[nt][0]) : "r"(x0));
            asm("ex2.approx.f16x2 %0, %1;" : "=r"(pf[nt][1]) : "r"(x1));
            float2 f0 = __half22float2(*(__half2*)&pf[nt][0]);
            float2 f1 = __half22float2(*(__half2*)&pf[nt][1]);
            ls0 += f0.x + f0.y;
            ls1 += f1.x + f1.y;
        }
        ls0 += __shfl_xor_sync(0xffffffffu, ls0, 1);
        ls0 += __shfl_xor_sync(0xffffffffu, ls0, 2);
        ls1 += __shfl_xor_sync(0xffffffffu, ls1, 1);
        ls1 += __shfl_xor_sync(0xffffffffu, ls1, 2);
        l0 = c0 * l0 + ls0;
        l1 = c1 * l1 + ls1;

#pragma unroll
        for (int dn = 0; dn < 16; dn++) {
            acc_o[dn][0] *= c0; acc_o[dn][1] *= c0;
            acc_o[dn][2] *= c1; acc_o[dn][3] *= c1;
        }

        // ---- O += P V ----
        const unsigned vb = vsb + cur * VS_U32 * 4;
#pragma unroll
        for (int dp = 0; dp < 8; dp++) {
#pragma unroll
            for (int kp = 0; kp < 4; kp++) {
                unsigned f0, f1, f2, f3;
                ldsm4(f0, f1, f2, f3,
                      vb + 4 * ((dp * 16 + b_row) * VROWU + kp * 8 + b_col));
                MMA16816(acc_o[2 * dp],     pf[2 * kp][0], pf[2 * kp][1],
                         pf[2 * kp + 1][0], pf[2 * kp + 1][1], f0, f1);
                MMA16816(acc_o[2 * dp + 1], pf[2 * kp][0], pf[2 * kp][1],
                         pf[2 * kp + 1][0], pf[2 * kp + 1][1], f2, f3);
            }
        }

        __syncthreads();
        if (kt + 2 < 32) ISSUE_KV(kt + 2, cur);
    }
#undef ISSUE_KV

    float inv0 = 1.0f / l0;
    float inv1 = 1.0f / l1;
    long t0 = (long)(b * 2048 + qt * 64 + wq * 16 + grp);
    long t1 = t0 + 8;
#pragma unroll
    for (int dn = 0; dn < 16; dn++) {
        int col = h * 128 + dn * 8 + tig * 2;
        *(unsigned*)&O[t0 * HID + col] = packh2(acc_o[dn][0] * inv0, acc_o[dn][1] * inv0);
        *(unsigned*)&O[t1 * HID + col] = packh2(acc_o[dn][2] * inv1, acc_o[dn][3] * inv1);
    }
}

// ---- single conversion kernel for all fp32->fp16 inputs --------------------
#define N_H 8388608L
#define N_W 4194304L
__global__ __launch_bounds__(256)
void f2h_all(const float* __restrict__ hidden, const float* __restrict__ Wq,
             const float* __restrict__ Wk, const float* __restrict__ Wv,
             const float* __restrict__ Wo, const float* __restrict__ mask,
             __half* __restrict__ h16, __half* __restrict__ wqk16,
             __half* __restrict__ wv16, __half* __restrict__ wo16,
             __half* __restrict__ m16)
{
    long i = ((long)blockIdx.x * 256 + threadIdx.x) * 4;
    const float* src;
    __half* dst;
    long off;
    if (i < N_H)               { src = hidden; dst = h16;          off = i; }
    else if (i < N_H + N_W)    { src = Wq;   dst = wqk16;          off = i - N_H; }
    else if (i < N_H + 2*N_W)  { src = Wk;   dst = wqk16 + N_W;    off = i - N_H - N_W; }
    else if (i < N_H + 3*N_W)  { src = Wv;   dst = wv16;           off = i - N_H - 2*N_W; }
    else if (i < N_H + 4*N_W)  { src = Wo;   dst = wo16;           off = i - N_H - 3*N_W; }
    else                       { src = mask; dst = m16;            off = i - N_H - 4*N_W; }
    float4 v = *(const float4*)&src[off];
    *(__half2*)&dst[off]     = __floats2half2_rn(v.x, v.y);
    *(__half2*)&dst[off + 2] = __floats2half2_rn(v.z, v.w);
}

extern "C" void kernel_launch(void* const* d_in, const int* in_sizes, int n_in,
                              void* d_out, int out_size)
{
    (void)in_sizes; (void)n_in; (void)out_size;
    const float* hidden = (const float*)d_in[0];
    const float* mask   = (const float*)d_in[1];
    const float* Wq     = (const float*)d_in[2];
    const float* Wk     = (const float*)d_in[3];
    const float* Wv     = (const float*)d_in[4];
    const float* Wo     = (const float*)d_in[5];
    float* out = (float*)d_out;

    __half *h16, *wqk16, *wv16, *wo16, *m16, *qk16, *vt16, *att16;
    cudaGetSymbolAddress((void**)&h16,   g_h16);
    cudaGetSymbolAddress((void**)&wqk16, g_wqk16);
    cudaGetSymbolAddress((void**)&wv16,  g_wv16);
    cudaGetSymbolAddress((void**)&wo16,  g_wo16);
    cudaGetSymbolAddress((void**)&m16,   g_m16);
    cudaGetSymbolAddress((void**)&qk16,  g_qk16);
    cudaGetSymbolAddress((void**)&vt16,  g_vt16);
    cudaGetSymbolAddress((void**)&att16, g_att16);

    cudaFuncSetAttribute(gemm_fused,
                         cudaFuncAttributeMaxDynamicSharedMemorySize, SMEM_BYTES16);
    cudaFuncSetAttribute(gemm_out,
                         cudaFuncAttributeMaxDynamicSharedMemorySize, SMEM_BYTES16);
    cudaFuncSetAttribute(flash_kernel,
                         cudaFuncAttributeMaxDynamicSharedMemorySize, FLASH_SMEM);

    // 0: all conversions in one launch (29,360,128 elems / 4 per thread)
    f2h_all<<<28672, 256>>>(hidden, Wq, Wk, Wv, Wo, mask,
                            h16, wqk16, wv16, wo16, m16);

    // 1: fused GEMM launch: qk16 (1024 CTAs) + vt16 (512 CTAs)
    gemm_fused<<<1536, 256, SMEM_BYTES16>>>(h16, wqk16, wv16, qk16, vt16);

    // 2: fused attention
    dim3 gFlash(32, 32, 1);
    flash_kernel<<<gFlash, dim3(128), FLASH_SMEM>>>(qk16, vt16, m16, att16);

    // 3: out = att16 @ Wo^T
    dim3 gOut(HID / BN, MROWS / BM, 1);
    gemm_out<<<gOut, dim3(256), SMEM_BYTES16>>>(att16, wo16, out);
}

// round 10
// speedup vs baseline: 6.8194x; 1.0683x over previous
#include <cuda_runtime.h>
#include <cuda_fp16.h>
#include <math.h>

// ---------------------------------------------------------------------------
// TensorParallelAttention — fp16 mma.sync + ldmatrix + f16x2 ex2 softmax.
// R10: GEMM mainloop -> 4-stage cp.async pipeline with ONE barrier per k-tile,
//      batched fragment LDSM (both k16 steps before MMA burst).
//   0. f2h_all: hidden,Wq|Wk,Wv,Wo,mask -> fp16 (one launch)
//   1. fused GEMM launch: qk16 = h16 @ [Wq|Wk]^T  AND  vt16 = Wv16 @ h16^T
//   2. flash: att16 = softmax(aQK^T+M)V   (mask prefetched to smem)
//   3. out  = att16 @ Wo^T
// ---------------------------------------------------------------------------

#define BM 128
#define BN 128
#define ROW_U32 20
#define STAGE_U32 (128 * ROW_U32)
#define NSTAGES 4
#define SMEM_BYTES16 (NSTAGES * 2 * STAGE_U32 * 4)   // 81920

#define HID 2048
#define MROWS 4096
#define QKLD 4096

#define KROW 68
#define VROWU 36
#define MROW_U32 36
#define QS_U32 (64 * KROW)
#define KS_U32 (64 * KROW)
#define VS_U32 (128 * VROWU)
#define MS_U32 (64 * MROW_U32)
#define FLASH_SMEM ((QS_U32 + 2 * KS_U32 + 2 * VS_U32 + 2 * MS_U32) * 4) // 107520

__device__ __half g_h16[MROWS * HID];
__device__ __half g_wqk16[2L * HID * HID];
__device__ __half g_wv16[HID * HID];
__device__ __half g_wo16[HID * HID];
__device__ __half g_m16[2048L * 2048];
__device__ __half g_qk16[(long)MROWS * QKLD];
__device__ __half g_vt16[MROWS * HID];
__device__ __half g_att16[MROWS * HID];

__device__ __forceinline__ void cp_async16(void* smem_dst, const void* gmem_src) {
    unsigned s = (unsigned)__cvta_generic_to_shared(smem_dst);
    asm volatile("cp.async.cg.shared.global [%0], [%1], 16;\n" :: "r"(s), "l"(gmem_src));
}
__device__ __forceinline__ void cp_commit() {
    asm volatile("cp.async.commit_group;\n");
}
template <int N> __device__ __forceinline__ void cp_wait() {
    asm volatile("cp.async.wait_group %0;\n" :: "n"(N));
}
__device__ __forceinline__ unsigned packh2(float a, float b) {
    __half2 h = __floats2half2_rn(a, b);
    return *(unsigned*)&h;
}
__device__ __forceinline__ void ldsm4(unsigned& r0, unsigned& r1,
                                      unsigned& r2, unsigned& r3, unsigned addr) {
    asm volatile("ldmatrix.sync.aligned.m8n8.x4.shared.b16 {%0,%1,%2,%3}, [%4];"
                 : "=r"(r0), "=r"(r1), "=r"(r2), "=r"(r3) : "r"(addr));
}
#define MMA16816(D, A0, A1, A2, A3, B0, B1)                                     \
    asm volatile(                                                               \
        "mma.sync.aligned.m16n8k16.row.col.f32.f16.f16.f32 "                    \
        "{%0,%1,%2,%3}, {%4,%5,%6,%7}, {%8,%9}, {%0,%1,%2,%3};"                 \
        : "+f"((D)[0]), "+f"((D)[1]), "+f"((D)[2]), "+f"((D)[3])                \
        : "r"(A0), "r"(A1), "r"(A2), "r"(A3), "r"(B0), "r"(B1))

// ---------------- GEMM body: 4-stage, 1 barrier/tile, batched LDSM ----------
// C[M,N] = alpha * A @ B^T ; A:[M,K] k-contig fp16, B:[N,K] k-contig fp16.
template <typename OutT>
__device__ __forceinline__
void gemm_body(const __half* __restrict__ A, const __half* __restrict__ B,
               OutT* __restrict__ C, int K, int lda, int ldb, int ldc,
               float alpha, int bm, int bn, unsigned* smem)
{
    const unsigned smb = (unsigned)__cvta_generic_to_shared(smem);

    const int tid  = threadIdx.x;
    const int lane = tid & 31;
    const int wid  = tid >> 5;
    const int grp  = lane >> 2;
    const int tig  = lane & 3;
    const int wm = wid & 1;
    const int wn = wid >> 1;

    const int a_row = ((lane >> 3) & 1) * 8 + (lane & 7);
    const int a_col = (lane >> 4) * 4;
    const int b_row = ((lane >> 4) << 3) + (lane & 7);
    const int b_col = ((lane >> 3) & 1) << 2;

    float acc[4][4][4];
#pragma unroll
    for (int i = 0; i < 4; i++)
#pragma unroll
        for (int j = 0; j < 4; j++)
#pragma unroll
            for (int t = 0; t < 4; t++) acc[i][j][t] = 0.0f;

    const int ntiles = K / 32;

#define ISSUE_TILE(KT, STAGE)                                                   \
    do {                                                                        \
        unsigned* as = smem + (STAGE) * STAGE_U32;                              \
        unsigned* bs = smem + (NSTAGES + (STAGE)) * STAGE_U32;                  \
        _Pragma("unroll")                                                       \
        for (int i = 0; i < 2; i++) {                                           \
            int linear = tid + i * 256;                                         \
            int r  = linear >> 2;                                               \
            int c4 = (linear & 3) << 2;                                         \
            cp_async16(&as[r * ROW_U32 + c4],                                   \
                       &A[(long)(bm + r) * lda + (KT) * 32 + c4 * 2]);          \
            cp_async16(&bs[r * ROW_U32 + c4],                                   \
                       &B[(long)(bn + r) * ldb + (KT) * 32 + c4 * 2]);          \
        }                                                                       \
        cp_commit();                                                            \
    } while (0)

    ISSUE_TILE(0, 0);
    ISSUE_TILE(1, 1);
    ISSUE_TILE(2, 2);

    for (int kt = 0; kt < ntiles; kt++) {
        const int cur = kt & 3;
        if (kt + 2 < ntiles)      cp_wait<2>();
        else if (kt + 1 < ntiles) cp_wait<1>();
        else                      cp_wait<0>();
        __syncthreads();

        const unsigned abase = smb + (cur * STAGE_U32) * 4;
        const unsigned bbase = smb + ((NSTAGES + cur) * STAGE_U32) * 4;

        // batched fragment loads: both k16 steps (12 LDSM) before 32 MMAs
        unsigned af[2][4][4], bf[2][4][2];
#pragma unroll
        for (int s = 0; s < 2; s++) {
            const int p0 = s * 8;
#pragma unroll
            for (int mt = 0; mt < 4; mt++)
                ldsm4(af[s][mt][0], af[s][mt][1], af[s][mt][2], af[s][mt][3],
                      abase + 4 * ((wm * 64 + mt * 16 + a_row) * ROW_U32 + p0 + a_col));
#pragma unroll
            for (int np = 0; np < 2; np++)
                ldsm4(bf[s][2 * np][0], bf[s][2 * np][1],
                      bf[s][2 * np + 1][0], bf[s][2 * np + 1][1],
                      bbase + 4 * ((wn * 32 + np * 16 + b_row) * ROW_U32 + p0 + b_col));
        }
#pragma unroll
        for (int s = 0; s < 2; s++)
#pragma unroll
            for (int mt = 0; mt < 4; mt++)
#pragma unroll
                for (int nt = 0; nt < 4; nt++)
                    MMA16816(acc[mt][nt], af[s][mt][0], af[s][mt][1],
                             af[s][mt][2], af[s][mt][3],
                             bf[s][nt][0], bf[s][nt][1]);

        if (kt + 3 < ntiles) ISSUE_TILE(kt + 3, (kt + 3) & 3);
    }
#undef ISSUE_TILE

#pragma unroll
    for (int mt = 0; mt < 4; mt++) {
        int r0 = bm + wm * 64 + mt * 16 + grp;
        int r1 = r0 + 8;
#pragma unroll
        for (int nt = 0; nt < 4; nt++) {
            int c = bn + wn * 32 + nt * 8 + tig * 2;
            float x0 = acc[mt][nt][0] * alpha, x1 = acc[mt][nt][1] * alpha;
            float x2 = acc[mt][nt][2] * alpha, x3 = acc[mt][nt][3] * alpha;
            if (sizeof(OutT) == 2) {
                *(unsigned*)&((__half*)C)[(long)r0 * ldc + c] = packh2(x0, x1);
                *(unsigned*)&((__half*)C)[(long)r1 * ldc + c] = packh2(x2, x3);
            } else {
                *(float2*)&((float*)C)[(long)r0 * ldc + c] = make_float2(x0, x1);
                *(float2*)&((float*)C)[(long)r1 * ldc + c] = make_float2(x2, x3);
            }
        }
    }
}

// Fused launch: z<1024 -> qk16 = h16 @ wqk16^T ; z>=1024 -> vt16 = wv16 @ h16^T
__global__ __launch_bounds__(256, 2)
void gemm_fused(const __half* __restrict__ h16, const __half* __restrict__ wqk16,
                const __half* __restrict__ wv16, __half* __restrict__ qk16,
                __half* __restrict__ vt16)
{
    extern __shared__ unsigned smem[];
    int z = blockIdx.x;
    if (z < 1024) {
        gemm_body<__half>(h16, wqk16, qk16, HID, HID, HID, QKLD, 1.0f,
                          (z >> 5) * 128, (z & 31) * 128, smem);
    } else {
        int y = z - 1024;
        gemm_body<__half>(wv16, h16, vt16, HID, HID, HID, MROWS, 1.0f,
                          (y >> 5) * 128, (y & 31) * 128, smem);
    }
}

// Output projection: out = att16 @ Wo^T (fp32)
__global__ __launch_bounds__(256, 2)
void gemm_out(const __half* __restrict__ att16, const __half* __restrict__ wo16,
              float* __restrict__ out)
{
    extern __shared__ unsigned smem[];
    gemm_body<float>(att16, wo16, out, HID, HID, HID, HID, 1.0f,
                     blockIdx.y * BM, blockIdx.x * BN, smem);
}

// ---------------- fused flash attention (R9-verified) -----------------------
__global__ __launch_bounds__(128, 2)
void flash_kernel(const __half* __restrict__ QK, const __half* __restrict__ Vt,
                  const __half* __restrict__ M16, __half* __restrict__ O)
{
    extern __shared__ unsigned sm[];
    unsigned* Qs = sm;
    unsigned* Ks = sm + QS_U32;
    unsigned* Vs = sm + QS_U32 + 2 * KS_U32;
    unsigned* Ms = sm + QS_U32 + 2 * KS_U32 + 2 * VS_U32;
    const unsigned smb = (unsigned)__cvta_generic_to_shared(sm);
    const unsigned ksb = smb + QS_U32 * 4;
    const unsigned vsb = smb + (QS_U32 + 2 * KS_U32) * 4;

    const int tid  = threadIdx.x;
    const int lane = tid & 31;
    const int wq   = tid >> 5;
    const int grp  = lane >> 2;
    const int tig  = lane & 3;
    const int b_row = ((lane >> 4) << 3) + (lane & 7);
    const int b_col = ((lane >> 3) & 1) << 2;

    const int z  = blockIdx.y;
    const int b  = z >> 4;
    const int h  = z & 15;
    const int qt = blockIdx.x;

    const __half* Qg = QK + (long)(b * 2048 + qt * 64) * QKLD + h * 128;
    const __half* Kg = QK + (long)(b * 2048) * QKLD + 2048 + h * 128;
    const __half* Vg = Vt + (long)(h * 128) * (long)MROWS + b * 2048;
    const __half* Mg = M16 + (long)(qt * 64) * 2048;

#define ISSUE_KV(KT, STAGE)                                                     \
    do {                                                                        \
        unsigned* ks = Ks + (STAGE) * KS_U32;                                   \
        unsigned* vs = Vs + (STAGE) * VS_U32;                                   \
        unsigned* ms = Ms + (STAGE) * MS_U32;                                   \
        _Pragma("unroll")                                                       \
        for (int i = 0; i < 8; i++) {                                           \
            int lin = tid + i * 128;                                            \
            int kr  = lin >> 4;                                                 \
            int kc  = (lin & 15) << 2;                                          \
            cp_async16(&ks[kr * KROW + kc],                                     \
                       Kg + (long)((KT) * 64 + kr) * QKLD + kc * 2);            \
            int vr  = lin >> 3;                                                 \
            int vc  = (lin & 7) << 2;                                           \
            cp_async16(&vs[vr * VROWU + vc],                                    \
                       Vg + (long)vr * MROWS + (KT) * 64 + vc * 2);             \
        }                                                                       \
        _Pragma("unroll")                                                       \
        for (int i = 0; i < 4; i++) {                                           \
            int lin = tid + i * 128;                                            \
            int mr  = lin >> 3;                                                 \
            int mc  = (lin & 7) << 2;                                           \
            cp_async16(&ms[mr * MROW_U32 + mc],                                 \
                       Mg + (long)mr * 2048 + (KT) * 64 + mc * 2);              \
        }                                                                       \
        cp_commit();                                                            \
    } while (0)

#pragma unroll
    for (int i = 0; i < 8; i++) {
        int lin = tid + i * 128;
        int r  = lin >> 4;
        int c4 = (lin & 15) << 2;
        cp_async16(&Qs[r * KROW + c4], Qg + (long)r * QKLD + c4 * 2);
    }
    ISSUE_KV(0, 0);
    ISSUE_KV(1, 1);

    float acc_o[16][4];
#pragma unroll
    for (int i = 0; i < 16; i++)
#pragma unroll
        for (int t = 0; t < 4; t++) acc_o[i][t] = 0.0f;
    float m0 = -1e30f, m1 = -1e30f, l0 = 0.0f, l1 = 0.0f;
    unsigned qf[8][4];

    const float alpha = 0.08838834764831845f;
    const float LOG2E = 1.44269504f;

    for (int kt = 0; kt < 32; kt++) {
        const int cur = kt & 1;
        if (kt + 1 < 32) cp_wait<1>(); else cp_wait<0>();
        __syncthreads();

        if (kt == 0) {
#pragma unroll
            for (int ks = 0; ks < 8; ks++) {
                int m = wq * 16 + grp;
                qf[ks][0] = Qs[m * KROW + ks * 8 + tig];
                qf[ks][1] = Qs[(m + 8) * KROW + ks * 8 + tig];
                qf[ks][2] = Qs[m * KROW + ks * 8 + tig + 4];
                qf[ks][3] = Qs[(m + 8) * KROW + ks * 8 + tig + 4];
            }
        }

        // ---- S = Q K^T ----
        float s[8][4];
#pragma unroll
        for (int nt = 0; nt < 8; nt++)
#pragma unroll
            for (int t = 0; t < 4; t++) s[nt][t] = 0.0f;

        const unsigned kb = ksb + cur * KS_U32 * 4;
#pragma unroll
        for (int np = 0; np < 4; np++) {
#pragma unroll
            for (int ks = 0; ks < 8; ks++) {
                unsigned f0, f1, f2, f3;
                ldsm4(f0, f1, f2, f3,
                      kb + 4 * ((np * 16 + b_row) * KROW + ks * 8 + b_col));
                MMA16816(s[2 * np],     qf[ks][0], qf[ks][1], qf[ks][2], qf[ks][3], f0, f1);
                MMA16816(s[2 * np + 1], qf[ks][0], qf[ks][1], qf[ks][2], qf[ks][3], f2, f3);
            }
        }

        // ---- scale + mask (smem) + online softmax (f16x2 ex2) ----
        const int qr0 = wq * 16 + grp;
        const unsigned* msm = Ms + cur * MS_U32;
        float mn0 = m0, mn1 = m1;
#pragma unroll
        for (int nt = 0; nt < 8; nt++) {
            unsigned u0 = msm[qr0 * MROW_U32 + nt * 4 + tig];
            unsigned u1 = msm[(qr0 + 8) * MROW_U32 + nt * 4 + tig];
            float2 mk0 = __half22float2(*(__half2*)&u0);
            float2 mk1 = __half22float2(*(__half2*)&u1);
            s[nt][0] = fmaf(s[nt][0], alpha, mk0.x);
            s[nt][1] = fmaf(s[nt][1], alpha, mk0.y);
            s[nt][2] = fmaf(s[nt][2], alpha, mk1.x);
            s[nt][3] = fmaf(s[nt][3], alpha, mk1.y);
            mn0 = fmaxf(mn0, fmaxf(s[nt][0], s[nt][1]));
            mn1 = fmaxf(mn1, fmaxf(s[nt][2], s[nt][3]));
        }
        mn0 = fmaxf(mn0, __shfl_xor_sync(0xffffffffu, mn0, 1));
        mn0 = fmaxf(mn0, __shfl_xor_sync(0xffffffffu, mn0, 2));
        mn1 = fmaxf(mn1, __shfl_xor_sync(0xffffffffu, mn1, 1));
        mn1 = fmaxf(mn1, __shfl_xor_sync(0xffffffffu, mn1, 2));

        float c0 = __expf(m0 - mn0);
        float c1 = __expf(m1 - mn1);
        m0 = mn0; m1 = mn1;
        const float mn0L = mn0 * LOG2E;
        const float mn1L = mn1 * LOG2E;

        unsigned pf[8][2];
        float ls0 = 0.0f, ls1 = 0.0f;
#pragma unroll
        for (int nt = 0; nt < 8; nt++) {
            float t0 = fmaf(s[nt][0], LOG2E, -mn0L);
            float t1 = fmaf(s[nt][1], LOG2E, -mn0L);
            float t2 = fmaf(s[nt][2], LOG2E, -mn1L);
            float t3 = fmaf(s[nt][3], LOG2E, -mn1L);
            unsigned x0 = packh2(t0, t1);
            unsigned x1 = packh2(t2, t3);
            asm("ex2.approx.f16x2 %0, %1;" : "=r"(pf[nt][0]) : "r"(x0));
            asm("ex2.approx.f16x2 %0, %1;" : "=r"(pf[nt][1]) : "r"(x1));
            float2 f0 = __half22float2(*(__half2*)&pf[nt][0]);
            float2 f1 = __half22float2(*(__half2*)&pf[nt][1]);
            ls0 += f0.x + f0.y;
            ls1 += f1.x + f1.y;
        }
        ls0 += __shfl_xor_sync(0xffffffffu, ls0, 1);
        ls0 += __shfl_xor_sync(0xffffffffu, ls0, 2);
        ls1 += __shfl_xor_sync(0xffffffffu, ls1, 1);
        ls1 += __shfl_xor_sync(0xffffffffu, ls1, 2);
        l0 = c0 * l0 + ls0;
        l1 = c1 * l1 + ls1;

#pragma unroll
        for (int dn = 0; dn < 16; dn++) {
            acc_o[dn][0] *= c0; acc_o[dn][1] *= c0;
            acc_o[dn][2] *= c1; acc_o[dn][3] *= c1;
        }

        // ---- O += P V ----
        const unsigned vb = vsb + cur * VS_U32 * 4;
#pragma unroll
        for (int dp = 0; dp < 8; dp++) {
#pragma unroll
            for (int kp = 0; kp < 4; kp++) {
                unsigned f0, f1, f2, f3;
                ldsm4(f0, f1, f2, f3,
                      vb + 4 * ((dp * 16 + b_row) * VROWU + kp * 8 + b_col));
                MMA16816(acc_o[2 * dp],     pf[2 * kp][0], pf[2 * kp][1],
                         pf[2 * kp + 1][0], pf[2 * kp + 1][1], f0, f1);
                MMA16816(acc_o[2 * dp + 1], pf[2 * kp][0], pf[2 * kp][1],
                         pf[2 * kp + 1][0], pf[2 * kp + 1][1], f2, f3);
            }
        }

        __syncthreads();
        if (kt + 2 < 32) ISSUE_KV(kt + 2, cur);
    }
#undef ISSUE_KV

    float inv0 = 1.0f / l0;
    float inv1 = 1.0f / l1;
    long t0 = (long)(b * 2048 + qt * 64 + wq * 16 + grp);
    long t1 = t0 + 8;
#pragma unroll
    for (int dn = 0; dn < 16; dn++) {
        int col = h * 128 + dn * 8 + tig * 2;
        *(unsigned*)&O[t0 * HID + col] = packh2(acc_o[dn][0] * inv0, acc_o[dn][1] * inv0);
        *(unsigned*)&O[t1 * HID + col] = packh2(acc_o[dn][2] * inv1, acc_o[dn][3] * inv1);
    }
}

// ---- single conversion kernel, 8 elems/thread ------------------------------
#define N_H 8388608L
#define N_W 4194304L
__global__ __launch_bounds__(256)
void f2h_all(const float* __restrict__ hidden, const float* __restrict__ Wq,
             const float* __restrict__ Wk, const float* __restrict__ Wv,
             const float* __restrict__ Wo, const float* __restrict__ mask,
             __half* __restrict__ h16, __half* __restrict__ wqk16,
             __half* __restrict__ wv16, __half* __restrict__ wo16,
             __half* __restrict__ m16)
{
    long i = ((long)blockIdx.x * 256 + threadIdx.x) * 8;
    const float* src;
    __half* dst;
    long off;
    if (i < N_H)               { src = hidden; dst = h16;          off = i; }
    else if (i < N_H + N_W)    { src = Wq;   dst = wqk16;          off = i - N_H; }
    else if (i < N_H + 2*N_W)  { src = Wk;   dst = wqk16 + N_W;    off = i - N_H - N_W; }
    else if (i < N_H + 3*N_W)  { src = Wv;   dst = wv16;           off = i - N_H - 2*N_W; }
    else if (i < N_H + 4*N_W)  { src = Wo;   dst = wo16;           off = i - N_H - 3*N_W; }
    else                       { src = mask; dst = m16;            off = i - N_H - 4*N_W; }
    float4 v0 = *(const float4*)&src[off];
    float4 v1 = *(const float4*)&src[off + 4];
    *(__half2*)&dst[off]     = __floats2half2_rn(v0.x, v0.y);
    *(__half2*)&dst[off + 2] = __floats2half2_rn(v0.z, v0.w);
    *(__half2*)&dst[off + 4] = __floats2half2_rn(v1.x, v1.y);
    *(__half2*)&dst[off + 6] = __floats2half2_rn(v1.z, v1.w);
}

extern "C" void kernel_launch(void* const* d_in, const int* in_sizes, int n_in,
                              void* d_out, int out_size)
{
    (void)in_sizes; (void)n_in; (void)out_size;
    const float* hidden = (const float*)d_in[0];
    const float* mask   = (const float*)d_in[1];
    const float* Wq     = (const float*)d_in[2];
    const float* Wk     = (const float*)d_in[3];
    const float* Wv     = (const float*)d_in[4];
    const float* Wo     = (const float*)d_in[5];
    float* out = (float*)d_out;

    __half *h16, *wqk16, *wv16, *wo16, *m16, *qk16, *vt16, *att16;
    cudaGetSymbolAddress((void**)&h16,   g_h16);
    cudaGetSymbolAddress((void**)&wqk16, g_wqk16);
    cudaGetSymbolAddress((void**)&wv16,  g_wv16);
    cudaGetSymbolAddress((void**)&wo16,  g_wo16);
    cudaGetSymbolAddress((void**)&m16,   g_m16);
    cudaGetSymbolAddress((void**)&qk16,  g_qk16);
    cudaGetSymbolAddress((void**)&vt16,  g_vt16);
    cudaGetSymbolAddress((void**)&att16, g_att16);

    cudaFuncSetAttribute(gemm_fused,
                         cudaFuncAttributeMaxDynamicSharedMemorySize, SMEM_BYTES16);
    cudaFuncSetAttribute(gemm_out,
                         cudaFuncAttributeMaxDynamicSharedMemorySize, SMEM_BYTES16);
    cudaFuncSetAttribute(flash_kernel,
                         cudaFuncAttributeMaxDynamicSharedMemorySize, FLASH_SMEM);

    // 0: all conversions (29,360,128 elems / 8 per thread)
    f2h_all<<<14336, 256>>>(hidden, Wq, Wk, Wv, Wo, mask,
                            h16, wqk16, wv16, wo16, m16);

    // 1: fused GEMM launch: qk16 (1024 CTAs) + vt16 (512 CTAs)
    gemm_fused<<<1536, 256, SMEM_BYTES16>>>(h16, wqk16, wv16, qk16, vt16);

    // 2: fused attention
    dim3 gFlash(32, 32, 1);
    flash_kernel<<<gFlash, dim3(128), FLASH_SMEM>>>(qk16, vt16, m16, att16);

    // 3: out = att16 @ Wo^T
    dim3 gOut(HID / BN, MROWS / BM, 1);
    gemm_out<<<gOut, dim3(256), SMEM_BYTES16>>>(att16, wo16, out);
}

// round 11
// speedup vs baseline: 6.8874x; 1.0100x over previous
#include <cuda_runtime.h>
#include <cuda_fp16.h>
#include <math.h>

// ---------------------------------------------------------------------------
// TensorParallelAttention — fp16 mma.sync + ldmatrix + f16x2 ex2 softmax.
// R11: GEMM BK=64 (1 barrier per 64-k tile, 3 stages);
//      flash software-pipelined: S(kt+1) interleaved with PV(kt).
//   0. f2h_all: hidden,Wq|Wk,Wv,Wo,mask -> fp16 (one launch)
//   1. fused GEMM launch: qk16 = h16 @ [Wq|Wk]^T  AND  vt16 = Wv16 @ h16^T
//   2. flash: att16 = softmax(aQK^T+M)V
//   3. out  = att16 @ Wo^T
// ---------------------------------------------------------------------------

#define BM 128
#define BN 128
#define GROW_U32 36                   // 32 data u32 (64 halves) + 4 pad
#define GSTAGE_U32 (128 * GROW_U32)   // 4608
#define GNSTAGES 3
#define SMEM_BYTES16 (GNSTAGES * 2 * GSTAGE_U32 * 4)   // 110592

#define HID 2048
#define MROWS 4096
#define QKLD 4096

#define KROW 68
#define VROWU 36
#define MROW_U32 36
#define QS_U32 (64 * KROW)
#define KS_U32 (64 * KROW)
#define VS_U32 (128 * VROWU)
#define MS_U32 (64 * MROW_U32)
#define FLASH_SMEM ((QS_U32 + 2 * KS_U32 + 2 * VS_U32 + 2 * MS_U32) * 4) // 107520

__device__ __half g_h16[MROWS * HID];
__device__ __half g_wqk16[2L * HID * HID];
__device__ __half g_wv16[HID * HID];
__device__ __half g_wo16[HID * HID];
__device__ __half g_m16[2048L * 2048];
__device__ __half g_qk16[(long)MROWS * QKLD];
__device__ __half g_vt16[MROWS * HID];
__device__ __half g_att16[MROWS * HID];

__device__ __forceinline__ void cp_async16(void* smem_dst, const void* gmem_src) {
    unsigned s = (unsigned)__cvta_generic_to_shared(smem_dst);
    asm volatile("cp.async.cg.shared.global [%0], [%1], 16;\n" :: "r"(s), "l"(gmem_src));
}
__device__ __forceinline__ void cp_commit() {
    asm volatile("cp.async.commit_group;\n");
}
template <int N> __device__ __forceinline__ void cp_wait() {
    asm volatile("cp.async.wait_group %0;\n" :: "n"(N));
}
__device__ __forceinline__ unsigned packh2(float a, float b) {
    __half2 h = __floats2half2_rn(a, b);
    return *(unsigned*)&h;
}
__device__ __forceinline__ void ldsm4(unsigned& r0, unsigned& r1,
                                      unsigned& r2, unsigned& r3, unsigned addr) {
    asm volatile("ldmatrix.sync.aligned.m8n8.x4.shared.b16 {%0,%1,%2,%3}, [%4];"
                 : "=r"(r0), "=r"(r1), "=r"(r2), "=r"(r3) : "r"(addr));
}
#define MMA16816(D, A0, A1, A2, A3, B0, B1)                                     \
    asm volatile(                                                               \
        "mma.sync.aligned.m16n8k16.row.col.f32.f16.f16.f32 "                    \
        "{%0,%1,%2,%3}, {%4,%5,%6,%7}, {%8,%9}, {%0,%1,%2,%3};"                 \
        : "+f"((D)[0]), "+f"((D)[1]), "+f"((D)[2]), "+f"((D)[3])                \
        : "r"(A0), "r"(A1), "r"(A2), "r"(A3), "r"(B0), "r"(B1))

// ---------------- GEMM body: BK=64, 3 stages, 1 barrier/tile ----------------
// C[M,N] = alpha * A @ B^T ; A:[M,K] k-contig fp16, B:[N,K] k-contig fp16.
template <typename OutT>
__device__ __forceinline__
void gemm_body(const __half* __restrict__ A, const __half* __restrict__ B,
               OutT* __restrict__ C, int K, int lda, int ldb, int ldc,
               float alpha, int bm, int bn, unsigned* smem)
{
    const unsigned smb = (unsigned)__cvta_generic_to_shared(smem);

    const int tid  = threadIdx.x;
    const int lane = tid & 31;
    const int wid  = tid >> 5;
    const int grp  = lane >> 2;
    const int tig  = lane & 3;
    const int wm = wid & 1;
    const int wn = wid >> 1;

    const int a_row = ((lane >> 3) & 1) * 8 + (lane & 7);
    const int a_col = (lane >> 4) * 4;
    const int b_row = ((lane >> 4) << 3) + (lane & 7);
    const int b_col = ((lane >> 3) & 1) << 2;

    float acc[4][4][4];
#pragma unroll
    for (int i = 0; i < 4; i++)
#pragma unroll
        for (int j = 0; j < 4; j++)
#pragma unroll
            for (int t = 0; t < 4; t++) acc[i][j][t] = 0.0f;

    const int ntiles = K / 64;

#define ISSUE_TILE(KT, STAGE)                                                   \
    do {                                                                        \
        unsigned* as = smem + (STAGE) * GSTAGE_U32;                             \
        unsigned* bs = smem + (GNSTAGES + (STAGE)) * GSTAGE_U32;                \
        _Pragma("unroll")                                                       \
        for (int i = 0; i < 4; i++) {                                           \
            int linear = tid + i * 256;                                         \
            int r  = linear >> 3;                                               \
            int c4 = (linear & 7) << 2;                                         \
            cp_async16(&as[r * GROW_U32 + c4],                                  \
                       &A[(long)(bm + r) * lda + (KT) * 64 + c4 * 2]);          \
            cp_async16(&bs[r * GROW_U32 + c4],                                  \
                       &B[(long)(bn + r) * ldb + (KT) * 64 + c4 * 2]);          \
        }                                                                       \
        cp_commit();                                                            \
    } while (0)

    ISSUE_TILE(0, 0);
    ISSUE_TILE(1, 1);

    for (int kt = 0; kt < ntiles; kt++) {
        const int cur = kt % 3;
        if (kt + 1 < ntiles) cp_wait<1>(); else cp_wait<0>();
        __syncthreads();
        if (kt + 2 < ntiles) ISSUE_TILE(kt + 2, (kt + 2) % 3);

        const unsigned abase = smb + (cur * GSTAGE_U32) * 4;
        const unsigned bbase = smb + ((GNSTAGES + cur) * GSTAGE_U32) * 4;

#pragma unroll
        for (int s2 = 0; s2 < 2; s2++) {
            unsigned af[2][4][4], bf[2][4][2];
#pragma unroll
            for (int s = 0; s < 2; s++) {
                const int p0 = s2 * 16 + s * 8;
#pragma unroll
                for (int mt = 0; mt < 4; mt++)
                    ldsm4(af[s][mt][0], af[s][mt][1], af[s][mt][2], af[s][mt][3],
                          abase + 4 * ((wm * 64 + mt * 16 + a_row) * GROW_U32 + p0 + a_col));
#pragma unroll
                for (int np = 0; np < 2; np++)
                    ldsm4(bf[s][2 * np][0], bf[s][2 * np][1],
                          bf[s][2 * np + 1][0], bf[s][2 * np + 1][1],
                          bbase + 4 * ((wn * 32 + np * 16 + b_row) * GROW_U32 + p0 + b_col));
            }
#pragma unroll
            for (int s = 0; s < 2; s++)
#pragma unroll
                for (int mt = 0; mt < 4; mt++)
#pragma unroll
                    for (int nt = 0; nt < 4; nt++)
                        MMA16816(acc[mt][nt], af[s][mt][0], af[s][mt][1],
                                 af[s][mt][2], af[s][mt][3],
                                 bf[s][nt][0], bf[s][nt][1]);
        }
    }
#undef ISSUE_TILE

#pragma unroll
    for (int mt = 0; mt < 4; mt++) {
        int r0 = bm + wm * 64 + mt * 16 + grp;
        int r1 = r0 + 8;
#pragma unroll
        for (int nt = 0; nt < 4; nt++) {
            int c = bn + wn * 32 + nt * 8 + tig * 2;
            float x0 = acc[mt][nt][0] * alpha, x1 = acc[mt][nt][1] * alpha;
            float x2 = acc[mt][nt][2] * alpha, x3 = acc[mt][nt][3] * alpha;
            if (sizeof(OutT) == 2) {
                *(unsigned*)&((__half*)C)[(long)r0 * ldc + c] = packh2(x0, x1);
                *(unsigned*)&((__half*)C)[(long)r1 * ldc + c] = packh2(x2, x3);
            } else {
                *(float2*)&((float*)C)[(long)r0 * ldc + c] = make_float2(x0, x1);
                *(float2*)&((float*)C)[(long)r1 * ldc + c] = make_float2(x2, x3);
            }
        }
    }
}

// Fused launch: z<1024 -> qk16 = h16 @ wqk16^T ; z>=1024 -> vt16 = wv16 @ h16^T
__global__ __launch_bounds__(256, 2)
void gemm_fused(const __half* __restrict__ h16, const __half* __restrict__ wqk16,
                const __half* __restrict__ wv16, __half* __restrict__ qk16,
                __half* __restrict__ vt16)
{
    extern __shared__ unsigned smem[];
    int z = blockIdx.x;
    if (z < 1024) {
        gemm_body<__half>(h16, wqk16, qk16, HID, HID, HID, QKLD, 1.0f,
                          (z >> 5) * 128, (z & 31) * 128, smem);
    } else {
        int y = z - 1024;
        gemm_body<__half>(wv16, h16, vt16, HID, HID, HID, MROWS, 1.0f,
                          (y >> 5) * 128, (y & 31) * 128, smem);
    }
}

__global__ __launch_bounds__(256, 2)
void gemm_out(const __half* __restrict__ att16, const __half* __restrict__ wo16,
              float* __restrict__ out)
{
    extern __shared__ unsigned smem[];
    gemm_body<float>(att16, wo16, out, HID, HID, HID, HID, 1.0f,
                     blockIdx.y * BM, blockIdx.x * BN, smem);
}

// ---------------- flash: S(kt+1) pipelined + interleaved with PV(kt) --------
__global__ __launch_bounds__(128, 2)
void flash_kernel(const __half* __restrict__ QK, const __half* __restrict__ Vt,
                  const __half* __restrict__ M16, __half* __restrict__ O)
{
    extern __shared__ unsigned sm[];
    unsigned* Qs = sm;
    unsigned* Ks = sm + QS_U32;
    unsigned* Vs = sm + QS_U32 + 2 * KS_U32;
    unsigned* Ms = sm + QS_U32 + 2 * KS_U32 + 2 * VS_U32;
    const unsigned smb = (unsigned)__cvta_generic_to_shared(sm);
    const unsigned ksb = smb + QS_U32 * 4;
    const unsigned vsb = smb + (QS_U32 + 2 * KS_U32) * 4;

    const int tid  = threadIdx.x;
    const int lane = tid & 31;
    const int wq   = tid >> 5;
    const int grp  = lane >> 2;
    const int tig  = lane & 3;
    const int b_row = ((lane >> 4) << 3) + (lane & 7);
    const int b_col = ((lane >> 3) & 1) << 2;

    const int z  = blockIdx.y;
    const int b  = z >> 4;
    const int h  = z & 15;
    const int qt = blockIdx.x;

    const __half* Qg = QK + (long)(b * 2048 + qt * 64) * QKLD + h * 128;
    const __half* Kg = QK + (long)(b * 2048) * QKLD + 2048 + h * 128;
    const __half* Vg = Vt + (long)(h * 128) * (long)MROWS + b * 2048;
    const __half* Mg = M16 + (long)(qt * 64) * 2048;

#define ISSUE_K(KT, STAGE)                                                      \
    do {                                                                        \
        unsigned* ks = Ks + (STAGE) * KS_U32;                                   \
        _Pragma("unroll")                                                       \
        for (int i = 0; i < 8; i++) {                                           \
            int lin = tid + i * 128;                                            \
            int kr  = lin >> 4;                                                 \
            int kc  = (lin & 15) << 2;                                          \
            cp_async16(&ks[kr * KROW + kc],                                     \
                       Kg + (long)((KT) * 64 + kr) * QKLD + kc * 2);            \
        }                                                                       \
        cp_commit();                                                            \
    } while (0)

#define ISSUE_VM(KT, STAGE)                                                     \
    do {                                                                        \
        unsigned* vs = Vs + (STAGE) * VS_U32;                                   \
        unsigned* ms = Ms + (STAGE) * MS_U32;                                   \
        _Pragma("unroll")                                                       \
        for (int i = 0; i < 8; i++) {                                           \
            int lin = tid + i * 128;                                            \
            int vr  = lin >> 3;                                                 \
            int vc  = (lin & 7) << 2;                                           \
            cp_async16(&vs[vr * VROWU + vc],                                    \
                       Vg + (long)vr * MROWS + (KT) * 64 + vc * 2);             \
        }                                                                       \
        _Pragma("unroll")                                                       \
        for (int i = 0; i < 4; i++) {                                           \
            int lin = tid + i * 128;                                            \
            int mr  = lin >> 3;                                                 \
            int mc  = (lin & 7) << 2;                                           \
            cp_async16(&ms[mr * MROW_U32 + mc],                                 \
                       Mg + (long)mr * 2048 + (KT) * 64 + mc * 2);              \
        }                                                                       \
        cp_commit();                                                            \
    } while (0)

    // ---- prologue: group1 = Q + K0 + V0 + M0 ; group2 = K1 ; group3 = V1+M1
#pragma unroll
    for (int i = 0; i < 8; i++) {
        int lin = tid + i * 128;
        int r  = lin >> 4;
        int c4 = (lin & 15) << 2;
        cp_async16(&Qs[r * KROW + c4], Qg + (long)r * QKLD + c4 * 2);
    }
#pragma unroll
    for (int i = 0; i < 8; i++) {
        int lin = tid + i * 128;
        int kr  = lin >> 4;
        int kc  = (lin & 15) << 2;
        cp_async16(&Ks[kr * KROW + kc], Kg + (long)kr * QKLD + kc * 2);
    }
#pragma unroll
    for (int i = 0; i < 8; i++) {
        int lin = tid + i * 128;
        int vr  = lin >> 3;
        int vc  = (lin & 7) << 2;
        cp_async16(&Vs[vr * VROWU + vc], Vg + (long)vr * MROWS + vc * 2);
    }
#pragma unroll
    for (int i = 0; i < 4; i++) {
        int lin = tid + i * 128;
        int mr  = lin >> 3;
        int mc  = (lin & 7) << 2;
        cp_async16(&Ms[mr * MROW_U32 + mc], Mg + (long)mr * 2048 + mc * 2);
    }
    cp_commit();
    ISSUE_K(1, 1);
    ISSUE_VM(1, 1);

    float acc_o[16][4];
#pragma unroll
    for (int i = 0; i < 16; i++)
#pragma unroll
        for (int t = 0; t < 4; t++) acc_o[i][t] = 0.0f;
    float m0 = -1e30f, m1 = -1e30f, l0 = 0.0f, l1 = 0.0f;
    unsigned qf[8][4];

    const float alpha = 0.08838834764831845f;
    const float LOG2E = 1.44269504f;

    cp_wait<2>();          // group1 (Q,K0,V0,M0) done
    __syncthreads();

#pragma unroll
    for (int ks = 0; ks < 8; ks++) {
        int m = wq * 16 + grp;
        qf[ks][0] = Qs[m * KROW + ks * 8 + tig];
        qf[ks][1] = Qs[(m + 8) * KROW + ks * 8 + tig];
        qf[ks][2] = Qs[m * KROW + ks * 8 + tig + 4];
        qf[ks][3] = Qs[(m + 8) * KROW + ks * 8 + tig + 4];
    }

    // S(0) from K stage 0
    float s_cur[8][4];
#pragma unroll
    for (int nt = 0; nt < 8; nt++)
#pragma unroll
        for (int t = 0; t < 4; t++) s_cur[nt][t] = 0.0f;
#pragma unroll
    for (int np = 0; np < 4; np++) {
#pragma unroll
        for (int ks = 0; ks < 8; ks++) {
            unsigned f0, f1, f2, f3;
            ldsm4(f0, f1, f2, f3,
                  ksb + 4 * ((np * 16 + b_row) * KROW + ks * 8 + b_col));
            MMA16816(s_cur[2 * np],     qf[ks][0], qf[ks][1], qf[ks][2], qf[ks][3], f0, f1);
            MMA16816(s_cur[2 * np + 1], qf[ks][0], qf[ks][1], qf[ks][2], qf[ks][3], f2, f3);
        }
    }
    __syncthreads();   // all warps done reading K stage 0 before gK(2) overwrites it

    for (int kt = 0; kt < 32; kt++) {
        const int cur = kt & 1;
        if (kt + 2 < 32) ISSUE_K(kt + 2, cur);

        if (kt < 30)       { cp_wait<2>(); }
        else if (kt == 30) { cp_wait<1>(); }
        else               { cp_wait<0>(); }
        __syncthreads();

        // ---- softmax(kt) on s_cur (mask from smem stage cur) ----
        const int qr0 = wq * 16 + grp;
        const unsigned* msm = Ms + cur * MS_U32;
        float mn0 = m0, mn1 = m1;
#pragma unroll
        for (int nt = 0; nt < 8; nt++) {
            unsigned u0 = msm[qr0 * MROW_U32 + nt * 4 + tig];
            unsigned u1 = msm[(qr0 + 8) * MROW_U32 + nt * 4 + tig];
            float2 mk0 = __half22float2(*(__half2*)&u0);
            float2 mk1 = __half22float2(*(__half2*)&u1);
            s_cur[nt][0] = fmaf(s_cur[nt][0], alpha, mk0.x);
            s_cur[nt][1] = fmaf(s_cur[nt][1], alpha, mk0.y);
            s_cur[nt][2] = fmaf(s_cur[nt][2], alpha, mk1.x);
            s_cur[nt][3] = fmaf(s_cur[nt][3], alpha, mk1.y);
            mn0 = fmaxf(mn0, fmaxf(s_cur[nt][0], s_cur[nt][1]));
            mn1 = fmaxf(mn1, fmaxf(s_cur[nt][2], s_cur[nt][3]));
        }
        mn0 = fmaxf(mn0, __shfl_xor_sync(0xffffffffu, mn0, 1));
        mn0 = fmaxf(mn0, __shfl_xor_sync(0xffffffffu, mn0, 2));
        mn1 = fmaxf(mn1, __shfl_xor_sync(0xffffffffu, mn1, 1));
        mn1 = fmaxf(mn1, __shfl_xor_sync(0xffffffffu, mn1, 2));

        float c0 = __expf(m0 - mn0);
        float c1 = __expf(m1 - mn1);
        m0 = mn0; m1 = mn1;
        const float mn0L = mn0 * LOG2E;
        const float mn1L = mn1 * LOG2E;

        unsigned pf[8][2];
        float ls0 = 0.0f, ls1 = 0.0f;
#pragma unroll
        for (int nt = 0; nt < 8; nt++) {
            float t0 = fmaf(s_cur[nt][0], LOG2E, -mn0L);
            float t1 = fmaf(s_cur[nt][1], LOG2E, -mn0L);
            float t2 = fmaf(s_cur[nt][2], LOG2E, -mn1L);
            float t3 = fmaf(s_cur[nt][3], LOG2E, -mn1L);
            unsigned x0 = packh2(t0, t1);
            unsigned x1 = packh2(t2, t3);
            asm("ex2.approx.f16x2 %0, %1;" : "=r"(pf[nt][0]) : "r"(x0));
            asm("ex2.approx.f16x2 %0, %1;" : "=r"(pf[nt][1]) : "r"(x1));
            float2 f0 = __half22float2(*(__half2*)&pf[nt][0]);
            float2 f1 = __half22float2(*(__half2*)&pf[nt][1]);
            ls0 += f0.x + f0.y;
            ls1 += f1.x + f1.y;
        }
        ls0 += __shfl_xor_sync(0xffffffffu, ls0, 1);
        ls0 += __shfl_xor_sync(0xffffffffu, ls0, 2);
        ls1 += __shfl_xor_sync(0xffffffffu, ls1, 1);
        ls1 += __shfl_xor_sync(0xffffffffu, ls1, 2);
        l0 = c0 * l0 + ls0;
        l1 = c1 * l1 + ls1;

#pragma unroll
        for (int dn = 0; dn < 16; dn++) {
            acc_o[dn][0] *= c0; acc_o[dn][1] *= c0;
            acc_o[dn][2] *= c1; acc_o[dn][3] *= c1;
        }

        // ---- PV(kt) interleaved with S(kt+1) ----
        const unsigned vb = vsb + cur * VS_U32 * 4;
        if (kt + 1 < 32) {
            const unsigned kb = ksb + (cur ^ 1) * KS_U32 * 4;
            float s_nxt[8][4];
#pragma unroll
            for (int nt = 0; nt < 8; nt++)
#pragma unroll
                for (int t = 0; t < 4; t++) s_nxt[nt][t] = 0.0f;
#pragma unroll
            for (int i = 0; i < 32; i++) {
                {
                    int np = i >> 3, ks = i & 7;
                    unsigned f0, f1, f2, f3;
                    ldsm4(f0, f1, f2, f3,
                          kb + 4 * ((np * 16 + b_row) * KROW + ks * 8 + b_col));
                    MMA16816(s_nxt[2 * np],     qf[ks][0], qf[ks][1], qf[ks][2], qf[ks][3], f0, f1);
                    MMA16816(s_nxt[2 * np + 1], qf[ks][0], qf[ks][1], qf[ks][2], qf[ks][3], f2, f3);
                }
                {
                    int dp = i >> 2, kp = i & 3;
                    unsigned g0, g1, g2, g3;
                    ldsm4(g0, g1, g2, g3,
                          vb + 4 * ((dp * 16 + b_row) * VROWU + kp * 8 + b_col));
                    MMA16816(acc_o[2 * dp],     pf[2 * kp][0], pf[2 * kp][1],
                             pf[2 * kp + 1][0], pf[2 * kp + 1][1], g0, g1);
                    MMA16816(acc_o[2 * dp + 1], pf[2 * kp][0], pf[2 * kp][1],
                             pf[2 * kp + 1][0], pf[2 * kp + 1][1], g2, g3);
                }
            }
#pragma unroll
            for (int nt = 0; nt < 8; nt++)
#pragma unroll
                for (int t = 0; t < 4; t++) s_cur[nt][t] = s_nxt[nt][t];
        } else {
#pragma unroll
            for (int dp = 0; dp < 8; dp++) {
#pragma unroll
                for (int kp = 0; kp < 4; kp++) {
                    unsigned g0, g1, g2, g3;
                    ldsm4(g0, g1, g2, g3,
                          vb + 4 * ((dp * 16 + b_row) * VROWU + kp * 8 + b_col));
                    MMA16816(acc_o[2 * dp],     pf[2 * kp][0], pf[2 * kp][1],
                             pf[2 * kp + 1][0], pf[2 * kp + 1][1], g0, g1);
                    MMA16816(acc_o[2 * dp + 1], pf[2 * kp][0], pf[2 * kp][1],
                             pf[2 * kp + 1][0], pf[2 * kp + 1][1], g2, g3);
                }
            }
        }

        __syncthreads();
        if (kt + 2 < 32) ISSUE_VM(kt + 2, cur);
    }
#undef ISSUE_K
#undef ISSUE_VM

    float inv0 = 1.0f / l0;
    float inv1 = 1.0f / l1;
    long t0 = (long)(b * 2048 + qt * 64 + wq * 16 + grp);
    long t1 = t0 + 8;
#pragma unroll
    for (int dn = 0; dn < 16; dn++) {
        int col = h * 128 + dn * 8 + tig * 2;
        *(unsigned*)&O[t0 * HID + col] = packh2(acc_o[dn][0] * inv0, acc_o[dn][1] * inv0);
        *(unsigned*)&O[t1 * HID + col] = packh2(acc_o[dn][2] * inv1, acc_o[dn][3] * inv1);
    }
}

// ---- single conversion kernel, 8 elems/thread ------------------------------
#define N_H 8388608L
#define N_W 4194304L
__global__ __launch_bounds__(256)
void f2h_all(const float* __restrict__ hidden, const float* __restrict__ Wq,
             const float* __restrict__ Wk, const float* __restrict__ Wv,
             const float* __restrict__ Wo, const float* __restrict__ mask,
             __half* __restrict__ h16, __half* __restrict__ wqk16,
             __half* __restrict__ wv16, __half* __restrict__ wo16,
             __half* __restrict__ m16)
{
    long i = ((long)blockIdx.x * 256 + threadIdx.x) * 8;
    const float* src;
    __half* dst;
    long off;
    if (i < N_H)               { src = hidden; dst = h16;          off = i; }
    else if (i < N_H + N_W)    { src = Wq;   dst = wqk16;          off = i - N_H; }
    else if (i < N_H + 2*N_W)  { src = Wk;   dst = wqk16 + N_W;    off = i - N_H - N_W; }
    else if (i < N_H + 3*N_W)  { src = Wv;   dst = wv16;           off = i - N_H - 2*N_W; }
    else if (i < N_H + 4*N_W)  { src = Wo;   dst = wo16;           off = i - N_H - 3*N_W; }
    else                       { src = mask; dst = m16;            off = i - N_H - 4*N_W; }
    float4 v0 = *(const float4*)&src[off];
    float4 v1 = *(const float4*)&src[off + 4];
    *(__half2*)&dst[off]     = __floats2half2_rn(v0.x, v0.y);
    *(__half2*)&dst[off + 2] = __floats2half2_rn(v0.z, v0.w);
    *(__half2*)&dst[off + 4] = __floats2half2_rn(v1.x, v1.y);
    *(__half2*)&dst[off + 6] = __floats2half2_rn(v1.z, v1.w);
}

extern "C" void kernel_launch(void* const* d_in, const int* in_sizes, int n_in,
                              void* d_out, int out_size)
{
    (void)in_sizes; (void)n_in; (void)out_size;
    const float* hidden = (const float*)d_in[0];
    const float* mask   = (const float*)d_in[1];
    const float* Wq     = (const float*)d_in[2];
    const float* Wk     = (const float*)d_in[3];
    const float* Wv     = (const float*)d_in[4];
    const float* Wo     = (const float*)d_in[5];
    float* out = (float*)d_out;

    __half *h16, *wqk16, *wv16, *wo16, *m16, *qk16, *vt16, *att16;
    cudaGetSymbolAddress((void**)&h16,   g_h16);
    cudaGetSymbolAddress((void**)&wqk16, g_wqk16);
    cudaGetSymbolAddress((void**)&wv16,  g_wv16);
    cudaGetSymbolAddress((void**)&wo16,  g_wo16);
    cudaGetSymbolAddress((void**)&m16,   g_m16);
    cudaGetSymbolAddress((void**)&qk16,  g_qk16);
    cudaGetSymbolAddress((void**)&vt16,  g_vt16);
    cudaGetSymbolAddress((void**)&att16, g_att16);

    cudaFuncSetAttribute(gemm_fused,
                         cudaFuncAttributeMaxDynamicSharedMemorySize, SMEM_BYTES16);
    cudaFuncSetAttribute(gemm_out,
                         cudaFuncAttributeMaxDynamicSharedMemorySize, SMEM_BYTES16);
    cudaFuncSetAttribute(flash_kernel,
                         cudaFuncAttributeMaxDynamicSharedMemorySize, FLASH_SMEM);

    // 0: all conversions
    f2h_all<<<14336, 256>>>(hidden, Wq, Wk, Wv, Wo, mask,
                            h16, wqk16, wv16, wo16, m16);

    // 1: fused GEMM launch: qk16 (1024 CTAs) + vt16 (512 CTAs)
    gemm_fused<<<1536, 256, SMEM_BYTES16>>>(h16, wqk16, wv16, qk16, vt16);

    // 2: fused attention
    dim3 gFlash(32, 32, 1);
    flash_kernel<<<gFlash, dim3(128), FLASH_SMEM>>>(qk16, vt16, m16, att16);

    // 3: out = att16 @ Wo^T
    dim3 gOut(HID / BN, MROWS / BM, 1);
    gemm_out<<<gOut, dim3(256), SMEM_BYTES16>>>(att16, wo16, out);
}